// round 11
// baseline (speedup 1.0000x reference)
#include <cuda_runtime.h>
#include <cuda_bf16.h>
#include <math.h>
#include <stdint.h>

#define BB 16
#define TLEN 2048
#define HH 512
#define BT (BB*TLEN)
#define KTOT 1536
#define NCH 32                // 32 channel-chunks of 16
#define NS 3                  // ring depth
#define NTILES 1024           // 16 b x 16 t-tiles x 4 o-tiles
#define PGRID 296             // 2 CTAs x 148 SMs, persistent
// per-stage smem layout (bytes from stage base):
//   Ahi: 130 rows x 48B          [0, 6240)
//   Alo:                          [6240, 12480)
//   B  : 6 tensors (s*2+h) x 128 rows x 32B (chunk-XOR swizzled)
#define ST_ALO  6240
#define ST_B    12480
#define B_T     4096
#define STAGE_B (ST_B + 6*B_T)   // 37056
#define DSMEM   (NS*STAGE_B)     // 111168

// static device scratch (no allocations)
__device__ __nv_bfloat16 g_Ahi[(size_t)BT*HH];
__device__ __nv_bfloat16 g_Alo[(size_t)BT*HH];
__device__ __nv_bfloat16 g_Whi[HH*KTOT];   // [o][klin], klin = s*512+i
__device__ __nv_bfloat16 g_Wlo[HH*KTOT];
__device__ float g_partial[BT*4];
__device__ float g_alpha[BT];
__device__ float g_cur[BT];
__device__ float g_remv[BT];
__device__ int   g_fire[BT];
__device__ int   g_nf[BB];

__device__ __forceinline__ uint32_t smem_u32(const void* p) {
    uint32_t r;
    asm("{ .reg .u64 t; cvta.to.shared.u64 t, %1; cvt.u32.u64 %0, t; }"
        : "=r"(r) : "l"(p));
    return r;
}
__device__ __forceinline__ void cp16(uint32_t dst, const void* src, int pb) {
    asm volatile("cp.async.cg.shared.global [%0], [%1], 16, %2;"
                 :: "r"(dst), "l"(src), "r"(pb));
}
__device__ __forceinline__ void ldx4(uint32_t* d, uint32_t addr) {
    asm volatile("ldmatrix.sync.aligned.m8n8.x4.shared.b16 {%0,%1,%2,%3}, [%4];"
                 : "=r"(d[0]), "=r"(d[1]), "=r"(d[2]), "=r"(d[3]) : "r"(addr));
}
#define MMA_BF16(c, a, b0, b1)                                              \
    asm volatile("mma.sync.aligned.m16n8k16.row.col.f32.bf16.bf16.f32 "     \
                 "{%0,%1,%2,%3}, {%4,%5,%6,%7}, {%8,%9}, {%0,%1,%2,%3};"    \
                 : "+f"((c)[0]), "+f"((c)[1]), "+f"((c)[2]), "+f"((c)[3])   \
                 : "r"((a)[0]), "r"((a)[1]), "r"((a)[2]), "r"((a)[3]),      \
                   "r"(b0), "r"(b1))

// ------------- prep: split hidden into bf16 hi/lo -------------
__global__ void k_hprep(const float* __restrict__ h) {
    size_t i = ((size_t)blockIdx.x * blockDim.x + threadIdx.x) * 4;
    float4 v = *(const float4*)(h + i);
    float vv[4] = {v.x, v.y, v.z, v.w};
    unsigned short hi[4], lo[4];
    #pragma unroll
    for (int k = 0; k < 4; k++) {
        __nv_bfloat16 hb = __float2bfloat16_rn(vv[k]);
        hi[k] = __bfloat16_as_ushort(hb);
        lo[k] = __bfloat16_as_ushort(__float2bfloat16_rn(vv[k] - __bfloat162float(hb)));
    }
    uint2 ph, pl;
    ph.x = (uint32_t)hi[0] | ((uint32_t)hi[1] << 16);
    ph.y = (uint32_t)hi[2] | ((uint32_t)hi[3] << 16);
    pl.x = (uint32_t)lo[0] | ((uint32_t)lo[1] << 16);
    pl.y = (uint32_t)lo[2] | ((uint32_t)lo[3] << 16);
    *(uint2*)(&g_Ahi[i]) = ph;
    *(uint2*)(&g_Alo[i]) = pl;
}

// ------------- prep: conv_w[o][i][s] -> Wt[o][s*512+i], bf16 hi/lo ---------
__global__ void k_wprep(const float* __restrict__ cw) {
    int idx = blockIdx.x * 256 + threadIdx.x;
    if (idx >= HH * KTOT) return;
    int o = idx / KTOT;
    int klin = idx % KTOT;
    int s = klin >> 9, i = klin & 511;
    float v = cw[(o * HH + i) * 3 + s];
    __nv_bfloat16 h = __float2bfloat16_rn(v);
    g_Whi[idx] = h;
    g_Wlo[idx] = __float2bfloat16_rn(v - __bfloat162float(h));
}

// ------------- bf16-split tensor-core GEMM, persistent CTAs ---------------
// 296 persistent CTAs grid-stride over 1024 (b, t0, o0) tiles.
// Per tile: 32 chunk-iters, 3-stage ring, depth-2 lookahead, 1 barrier/chunk.
__global__ __launch_bounds__(256, 2)
void k_gemm(const float* __restrict__ hidden,
            const float* __restrict__ convb,
            const float* __restrict__ outw) {
    extern __shared__ __align__(16) unsigned char sbuf[];

    const int tid    = threadIdx.x;
    const int lane   = tid & 31;
    const int wid    = tid >> 5;
    const int warp_m = wid >> 2;     // 0..1
    const int warp_n = wid & 3;      // 0..3
    const uint32_t sb = smem_u32(sbuf);

    // ldmatrix lane->address selectors
    const int rowA = lane & 15;
    const int colA = (lane >> 4) << 3;
    const int rowB = (lane & 7) + ((lane >> 4) << 3);   // 0..15
    const int chunkB = (lane >> 3) & 1;                  // 16B chunk select
    const uint32_t rdoff = (uint32_t)(rowB * 32 + ((chunkB ^ ((rowB >> 2) & 1)) << 4));

    // B thread mapping (fixed per thread)
    const int browp = tid >> 1;        // 0..127
    const int bchk  = tid & 1;         // 16B chunk
    const uint32_t bwr = (uint32_t)(browp * 32 + ((bchk ^ ((browp >> 2) & 1)) << 4));

    const int quad = lane >> 2;   // 0..7
    const int pr   = lane & 3;    // 0..3
    float* sred = (float*)sbuf;   // 128*4 floats (overlaps stage0 A)

    for (int tile = blockIdx.x; tile < NTILES; tile += PGRID) {
        const int og = tile & 3;
        const int xt = tile >> 2;
        const int b  = xt >> 4;
        const int t0 = (xt & 15) * 128;
        const int o0 = og * 128;

        const __nv_bfloat16* Ahi = g_Ahi + (size_t)b * TLEN * HH;
        const __nv_bfloat16* Alo = g_Alo + (size_t)b * TLEN * HH;

        float acc[4][4][4];
        #pragma unroll
        for (int m = 0; m < 4; m++)
            #pragma unroll
            for (int n = 0; n < 4; n++)
                #pragma unroll
                for (int e = 0; e < 4; e++) acc[m][n][e] = 0.f;

        auto load_stage = [&](int c) {
            const uint32_t st = sb + (uint32_t)(c % NS) * STAGE_B;
            const int i0 = c * 16;
            // A: 130 rows x 2 tensors x 2 chunks = 520 ops
            #pragma unroll
            for (int j = 0; j < 3; j++) {
                int a = tid + j * 256;
                if (a < 520) {
                    int chunk  = a & 1;
                    int tensor = (a >> 1) & 1;
                    int row    = a >> 2;            // 0..129
                    int gt = t0 - 1 + row;
                    bool v = (gt >= 0) && (gt < TLEN);
                    int gtc = v ? gt : 0;
                    int pb  = v ? 16 : 0;
                    const __nv_bfloat16* src =
                        (tensor ? Alo : Ahi) + (size_t)gtc * HH + i0 + chunk * 8;
                    cp16(st + tensor * ST_ALO + row * 48 + chunk * 16, src, pb);
                }
            }
            // B: 6 tensors (s,h) x 128 rows x 2 chunks = 1536 ops
            #pragma unroll
            for (int j = 0; j < 6; j++) {
                int s = j >> 1, h = j & 1;
                const __nv_bfloat16* src =
                    (h ? g_Wlo : g_Whi) + (size_t)(o0 + browp) * KTOT + s * 512 + i0 + bchk * 8;
                cp16(st + ST_B + j * B_T + bwr, src, 16);
            }
            asm volatile("cp.async.commit_group;");
        };

        auto compute_stage = [&](int c) {
            const uint32_t st = sb + (uint32_t)(c % NS) * STAGE_B;
            #pragma unroll
            for (int s = 0; s < 3; s++) {
                uint32_t aH[4][4], aL[4][4], bH[4][2], bL[4][2];
                #pragma unroll
                for (int mf = 0; mf < 4; mf++) {
                    uint32_t off = (uint32_t)((warp_m * 64 + mf * 16 + rowA + s) * 48 + colA * 2);
                    ldx4(aH[mf], st + off);
                    ldx4(aL[mf], st + ST_ALO + off);
                }
                #pragma unroll
                for (int nh = 0; nh < 2; nh++) {
                    uint32_t offb = (uint32_t)((warp_n * 32 + nh * 16) * 32) + rdoff;
                    uint32_t d[4];
                    ldx4(d, st + ST_B + (s * 2 + 0) * B_T + offb);
                    bH[nh*2][0] = d[0]; bH[nh*2][1] = d[1];
                    bH[nh*2+1][0] = d[2]; bH[nh*2+1][1] = d[3];
                    ldx4(d, st + ST_B + (s * 2 + 1) * B_T + offb);
                    bL[nh*2][0] = d[0]; bL[nh*2][1] = d[1];
                    bL[nh*2+1][0] = d[2]; bL[nh*2+1][1] = d[3];
                }
                // term-major: per-accumulator order stays H*H -> H*L -> L*H
                #pragma unroll
                for (int mf = 0; mf < 4; mf++)
                    #pragma unroll
                    for (int nf = 0; nf < 4; nf++)
                        MMA_BF16(acc[mf][nf], aH[mf], bH[nf][0], bH[nf][1]);
                #pragma unroll
                for (int mf = 0; mf < 4; mf++)
                    #pragma unroll
                    for (int nf = 0; nf < 4; nf++)
                        MMA_BF16(acc[mf][nf], aH[mf], bL[nf][0], bL[nf][1]);
                #pragma unroll
                for (int mf = 0; mf < 4; mf++)
                    #pragma unroll
                    for (int nf = 0; nf < 4; nf++)
                        MMA_BF16(acc[mf][nf], aL[mf], bH[nf][0], bH[nf][1]);
            }
        };

        // ensure previous tile's epilogue reads of sred are complete
        __syncthreads();

        // prologue: depth-2 lookahead
        load_stage(0);
        load_stage(1);

        for (int c = 0; c < NCH; ++c) {
            asm volatile("cp.async.wait_group 1;");
            __syncthreads();
            if (c + 2 < NCH) {
                load_stage(c + 2);
            } else {
                asm volatile("cp.async.commit_group;");
            }
            compute_stage(c);
        }

        // epilogue: y = acc + conv_b + residual; relu; dot out_w; reduce
        const float* hb = hidden + (size_t)b * TLEN * HH;
        __syncthreads();

        #pragma unroll
        for (int mf = 0; mf < 4; mf++) {
            int rloc = warp_m * 64 + mf * 16 + quad;
            float sA = 0.f, sB = 0.f;
            #pragma unroll
            for (int nf = 0; nf < 4; nf++) {
                int col = o0 + warp_n * 32 + nf * 8 + pr * 2;
                float2 cb = *(const float2*)(convb + col);
                float2 w  = *(const float2*)(outw + col);
                float2 hA = *(const float2*)(hb + (size_t)(t0 + rloc) * HH + col);
                float2 hB = *(const float2*)(hb + (size_t)(t0 + rloc + 8) * HH + col);
                float y;
                y = fmaxf(acc[mf][nf][0] + cb.x + hA.x, 0.f); sA = fmaf(y, w.x, sA);
                y = fmaxf(acc[mf][nf][1] + cb.y + hA.y, 0.f); sA = fmaf(y, w.y, sA);
                y = fmaxf(acc[mf][nf][2] + cb.x + hB.x, 0.f); sB = fmaf(y, w.x, sB);
                y = fmaxf(acc[mf][nf][3] + cb.y + hB.y, 0.f); sB = fmaf(y, w.y, sB);
            }
            sA += __shfl_xor_sync(0xffffffffu, sA, 1);
            sA += __shfl_xor_sync(0xffffffffu, sA, 2);
            sB += __shfl_xor_sync(0xffffffffu, sB, 1);
            sB += __shfl_xor_sync(0xffffffffu, sB, 2);
            if (pr == 0) {
                sred[rloc * 4 + warp_n]       = sA;
                sred[(rloc + 8) * 4 + warp_n] = sB;
            }
        }
        __syncthreads();
        if (tid < 128) {
            float s = (sred[tid*4+0] + sred[tid*4+1]) + (sred[tid*4+2] + sred[tid*4+3]);
            g_partial[(size_t)(b * TLEN + t0 + tid) * 4 + og] = s;
        }
    }
}

// ---------------- combine partials -> sigmoid -> alpha ----------------
__global__ void k_alpha(const float* __restrict__ mask, const float* __restrict__ outb) {
    int i = blockIdx.x * 256 + threadIdx.x;
    if (i >= BT) return;
    float l = ((g_partial[i*4+0] + g_partial[i*4+1]) +
               (g_partial[i*4+2] + g_partial[i*4+3])) + outb[0];
    float a = 1.f / (1.f + expf(-l));
    a = fmaxf(a, 0.f);
    a *= mask[i];
    g_alpha[i] = a;
}

// ---------------- sequential CIF scan (branchless, pipelined) ----------------
__global__ void k_scan() {
    int b = blockIdx.x;
    if (threadIdx.x != 0) return;
    const float4* al4 = (const float4*)(g_alpha + b * TLEN);
    float4* cur4 = (float4*)(g_cur + b * TLEN);
    int base = b * TLEN;
    float integ = 0.f;
    int j = 0;
    float4 c0 = al4[0], c1 = al4[1];
    #pragma unroll 1
    for (int ch = 0; ch < TLEN / 8; ++ch) {
        float4 n0 = make_float4(0,0,0,0), n1 = make_float4(0,0,0,0);
        if (ch + 1 < TLEN / 8) { n0 = al4[(ch+1)*2]; n1 = al4[(ch+1)*2 + 1]; }
        float av[8] = {c0.x,c0.y,c0.z,c0.w,c1.x,c1.y,c1.z,c1.w};
        float cv[8];
        int tt = ch * 8;
        #pragma unroll
        for (int s = 0; s < 8; s++) {
            float alpha = av[s];
            float dist  = 1.0f - integ;
            integ = integ + alpha;
            bool fire = (integ >= 1.0f);
            float cur = fire ? dist : alpha;
            cv[s] = cur;
            g_fire[base + j] = tt + s;        // unconditional; overwritten if !fire
            g_remv[base + j] = alpha - cur;
            j += fire;
            integ = fire ? integ - 1.0f : integ;
        }
        cur4[ch*2]   = make_float4(cv[0], cv[1], cv[2], cv[3]);
        cur4[ch*2+1] = make_float4(cv[4], cv[5], cv[6], cv[7]);
        c0 = n0; c1 = n1;
    }
    g_nf[b] = j;
}

// ---------------- parallel output gather ----------------
__global__ void k_out(const float* __restrict__ hidden, float* __restrict__ out) {
    int j = blockIdx.x;
    int b = blockIdx.y;
    int c = threadIdx.x << 2;
    const float* hb = hidden + (size_t)b * TLEN * HH;
    float4 acc = make_float4(0.f, 0.f, 0.f, 0.f);
    if (j < g_nf[b]) {
        int tend = g_fire[b * TLEN + j];
        int ts = 0;
        if (j > 0) {
            int tp = g_fire[b * TLEN + j - 1];
            float rv = g_remv[b * TLEN + j - 1];
            float4 h = *(const float4*)(hb + (size_t)tp * HH + c);
            acc.x = rv * h.x; acc.y = rv * h.y; acc.z = rv * h.z; acc.w = rv * h.w;
            ts = tp + 1;
        }
        for (int t = ts; t <= tend; ++t) {
            float w = g_cur[b * TLEN + t];
            float4 h = *(const float4*)(hb + (size_t)t * HH + c);
            acc.x = fmaf(w, h.x, acc.x);
            acc.y = fmaf(w, h.y, acc.y);
            acc.z = fmaf(w, h.z, acc.z);
            acc.w = fmaf(w, h.w, acc.w);
        }
    }
    *(float4*)(out + (size_t)(b * TLEN + j) * HH + c) = acc;
}

extern "C" void kernel_launch(void* const* d_in, const int* in_sizes, int n_in,
                              void* d_out, int out_size) {
    const float* hidden = (const float*)d_in[0];
    const float* mask   = (const float*)d_in[1];
    const float* conv_w = (const float*)d_in[2];
    const float* conv_b = (const float*)d_in[3];
    const float* out_w  = (const float*)d_in[4];
    const float* out_b  = (const float*)d_in[5];
    float* out = (float*)d_out;

    cudaFuncSetAttribute(k_gemm, cudaFuncAttributeMaxDynamicSharedMemorySize, DSMEM);

    k_hprep<<<(BT*HH/4 + 255)/256, 256>>>(hidden);
    k_wprep<<<(HH*KTOT + 255)/256, 256>>>(conv_w);
    k_gemm<<<PGRID, 256, DSMEM>>>(hidden, conv_b, out_w);
    k_alpha<<<BT/256, 256>>>(mask, out_b);
    k_scan<<<16, 32>>>();
    dim3 go(TLEN, BB);
    k_out<<<go, 128>>>(hidden, out);
}

// round 12
// speedup vs baseline: 1.2595x; 1.2595x over previous
#include <cuda_runtime.h>
#include <cuda_bf16.h>
#include <math.h>
#include <stdint.h>

#define BB 16
#define TLEN 2048
#define HH 512
#define BT (BB*TLEN)
#define KTOT 1536
#define NCH 32                // 32 channel-chunks of 16
#define NS 3                  // ring depth
// per-stage smem layout (bytes from stage base):
//   Ahi: 130 rows x 48B          [0, 6240)
//   Alo:                          [6240, 12480)
//   B  : 6 tensors (s*2+h) x 128 rows x 32B (chunk-XOR swizzled)
#define ST_ALO  6240
#define ST_B    12480
#define B_T     4096
#define STAGE_B (ST_B + 6*B_T)   // 37056
#define DSMEM   (NS*STAGE_B)     // 111168

// static device scratch (no allocations)
__device__ __nv_bfloat16 g_Ahi[(size_t)BT*HH];
__device__ __nv_bfloat16 g_Alo[(size_t)BT*HH];
__device__ __nv_bfloat16 g_Whi[HH*KTOT];   // [o][klin], klin = s*512+i
__device__ __nv_bfloat16 g_Wlo[HH*KTOT];
__device__ float g_partial[BT*4];
__device__ float g_cur[BT];
__device__ float g_remv[BT];
__device__ int   g_fire[BT];
__device__ int   g_nf[BB];

__device__ __forceinline__ uint32_t smem_u32(const void* p) {
    uint32_t r;
    asm("{ .reg .u64 t; cvta.to.shared.u64 t, %1; cvt.u32.u64 %0, t; }"
        : "=r"(r) : "l"(p));
    return r;
}
__device__ __forceinline__ void cp16(uint32_t dst, const void* src, int pb) {
    asm volatile("cp.async.cg.shared.global [%0], [%1], 16, %2;"
                 :: "r"(dst), "l"(src), "r"(pb));
}
__device__ __forceinline__ void ldx4(uint32_t* d, uint32_t addr) {
    asm volatile("ldmatrix.sync.aligned.m8n8.x4.shared.b16 {%0,%1,%2,%3}, [%4];"
                 : "=r"(d[0]), "=r"(d[1]), "=r"(d[2]), "=r"(d[3]) : "r"(addr));
}
#define MMA_BF16(c, a, b0, b1)                                              \
    asm volatile("mma.sync.aligned.m16n8k16.row.col.f32.bf16.bf16.f32 "     \
                 "{%0,%1,%2,%3}, {%4,%5,%6,%7}, {%8,%9}, {%0,%1,%2,%3};"    \
                 : "+f"((c)[0]), "+f"((c)[1]), "+f"((c)[2]), "+f"((c)[3])   \
                 : "r"((a)[0]), "r"((a)[1]), "r"((a)[2]), "r"((a)[3]),      \
                   "r"(b0), "r"(b1))

// ------------- prep: split hidden into bf16 hi/lo -------------
__global__ void k_hprep(const float* __restrict__ h) {
    size_t i = ((size_t)blockIdx.x * blockDim.x + threadIdx.x) * 4;
    float4 v = *(const float4*)(h + i);
    float vv[4] = {v.x, v.y, v.z, v.w};
    unsigned short hi[4], lo[4];
    #pragma unroll
    for (int k = 0; k < 4; k++) {
        __nv_bfloat16 hb = __float2bfloat16_rn(vv[k]);
        hi[k] = __bfloat16_as_ushort(hb);
        lo[k] = __bfloat16_as_ushort(__float2bfloat16_rn(vv[k] - __bfloat162float(hb)));
    }
    uint2 ph, pl;
    ph.x = (uint32_t)hi[0] | ((uint32_t)hi[1] << 16);
    ph.y = (uint32_t)hi[2] | ((uint32_t)hi[3] << 16);
    pl.x = (uint32_t)lo[0] | ((uint32_t)lo[1] << 16);
    pl.y = (uint32_t)lo[2] | ((uint32_t)lo[3] << 16);
    *(uint2*)(&g_Ahi[i]) = ph;
    *(uint2*)(&g_Alo[i]) = pl;
}

// ------------- prep: conv_w[o][i][s] -> Wt[o][s*512+i], bf16 hi/lo ---------
__global__ void k_wprep(const float* __restrict__ cw) {
    int idx = blockIdx.x * 256 + threadIdx.x;
    if (idx >= HH * KTOT) return;
    int o = idx / KTOT;
    int klin = idx % KTOT;
    int s = klin >> 9, i = klin & 511;
    float v = cw[(o * HH + i) * 3 + s];
    __nv_bfloat16 h = __float2bfloat16_rn(v);
    g_Whi[idx] = h;
    g_Wlo[idx] = __float2bfloat16_rn(v - __bfloat162float(h));
}

// ------------- bf16-split tensor-core GEMM (R10 champion config) ----------
// CTA: 128 t x 128 o. 32 chunk-iters; 3-stage ring, depth-2 lookahead,
// one barrier/chunk, occ 2. B rows chunk-XOR swizzled -> conflict-free LDSM.
__global__ __launch_bounds__(256, 2)
void k_gemm(const float* __restrict__ hidden,
            const float* __restrict__ convb,
            const float* __restrict__ outw) {
    extern __shared__ __align__(16) unsigned char sbuf[];

    const int tid    = threadIdx.x;
    const int lane   = tid & 31;
    const int wid    = tid >> 5;
    const int warp_m = wid >> 2;     // 0..1
    const int warp_n = wid & 3;      // 0..3
    const int b      = blockIdx.x >> 4;
    const int t0     = (blockIdx.x & 15) * 128;
    const int o0     = blockIdx.y * 128;

    const __nv_bfloat16* Ahi = g_Ahi + (size_t)b * TLEN * HH;
    const __nv_bfloat16* Alo = g_Alo + (size_t)b * TLEN * HH;
    const uint32_t sb = smem_u32(sbuf);

    float acc[4][4][4];
    #pragma unroll
    for (int m = 0; m < 4; m++)
        #pragma unroll
        for (int n = 0; n < 4; n++)
            #pragma unroll
            for (int e = 0; e < 4; e++) acc[m][n][e] = 0.f;

    // ldmatrix lane->address selectors
    const int rowA = lane & 15;
    const int colA = (lane >> 4) << 3;
    const int rowB = (lane & 7) + ((lane >> 4) << 3);   // 0..15
    const int chunkB = (lane >> 3) & 1;                  // 16B chunk select
    const uint32_t rdoff = (uint32_t)(rowB * 32 + ((chunkB ^ ((rowB >> 2) & 1)) << 4));

    // B thread mapping (fixed per thread)
    const int browp = tid >> 1;        // 0..127
    const int bchk  = tid & 1;         // 16B chunk
    const uint32_t bwr = (uint32_t)(browp * 32 + ((bchk ^ ((browp >> 2) & 1)) << 4));

    auto load_stage = [&](int c) {
        const uint32_t st = sb + (uint32_t)(c % NS) * STAGE_B;
        const int i0 = c * 16;
        // A: 130 rows x 2 tensors x 2 chunks = 520 ops
        #pragma unroll
        for (int j = 0; j < 3; j++) {
            int a = tid + j * 256;
            if (a < 520) {
                int chunk  = a & 1;
                int tensor = (a >> 1) & 1;
                int row    = a >> 2;            // 0..129
                int gt = t0 - 1 + row;
                bool v = (gt >= 0) && (gt < TLEN);
                int gtc = v ? gt : 0;
                int pb  = v ? 16 : 0;
                const __nv_bfloat16* src =
                    (tensor ? Alo : Ahi) + (size_t)gtc * HH + i0 + chunk * 8;
                cp16(st + tensor * ST_ALO + row * 48 + chunk * 16, src, pb);
            }
        }
        // B: 6 tensors (s,h) x 128 rows x 2 chunks = 1536 ops
        #pragma unroll
        for (int j = 0; j < 6; j++) {
            int s = j >> 1, h = j & 1;
            const __nv_bfloat16* src =
                (h ? g_Wlo : g_Whi) + (size_t)(o0 + browp) * KTOT + s * 512 + i0 + bchk * 8;
            cp16(st + ST_B + j * B_T + bwr, src, 16);
        }
        asm volatile("cp.async.commit_group;");
    };

    auto compute_stage = [&](int c) {
        const uint32_t st = sb + (uint32_t)(c % NS) * STAGE_B;
        #pragma unroll
        for (int s = 0; s < 3; s++) {
            uint32_t aH[4][4], aL[4][4], bH[4][2], bL[4][2];
            #pragma unroll
            for (int mf = 0; mf < 4; mf++) {
                uint32_t off = (uint32_t)((warp_m * 64 + mf * 16 + rowA + s) * 48 + colA * 2);
                ldx4(aH[mf], st + off);
                ldx4(aL[mf], st + ST_ALO + off);
            }
            #pragma unroll
            for (int nh = 0; nh < 2; nh++) {
                uint32_t offb = (uint32_t)((warp_n * 32 + nh * 16) * 32) + rdoff;
                uint32_t d[4];
                ldx4(d, st + ST_B + (s * 2 + 0) * B_T + offb);
                bH[nh*2][0] = d[0]; bH[nh*2][1] = d[1];
                bH[nh*2+1][0] = d[2]; bH[nh*2+1][1] = d[3];
                ldx4(d, st + ST_B + (s * 2 + 1) * B_T + offb);
                bL[nh*2][0] = d[0]; bL[nh*2][1] = d[1];
                bL[nh*2+1][0] = d[2]; bL[nh*2+1][1] = d[3];
            }
            // term-major: per-accumulator order stays H*H -> H*L -> L*H
            #pragma unroll
            for (int mf = 0; mf < 4; mf++)
                #pragma unroll
                for (int nf = 0; nf < 4; nf++)
                    MMA_BF16(acc[mf][nf], aH[mf], bH[nf][0], bH[nf][1]);
            #pragma unroll
            for (int mf = 0; mf < 4; mf++)
                #pragma unroll
                for (int nf = 0; nf < 4; nf++)
                    MMA_BF16(acc[mf][nf], aH[mf], bL[nf][0], bL[nf][1]);
            #pragma unroll
            for (int mf = 0; mf < 4; mf++)
                #pragma unroll
                for (int nf = 0; nf < 4; nf++)
                    MMA_BF16(acc[mf][nf], aL[mf], bH[nf][0], bH[nf][1]);
        }
    };

    // prologue: depth-2 lookahead
    load_stage(0);
    load_stage(1);

    for (int c = 0; c < NCH; ++c) {
        asm volatile("cp.async.wait_group 1;");
        __syncthreads();
        if (c + 2 < NCH) {
            load_stage(c + 2);
        } else {
            asm volatile("cp.async.commit_group;");
        }
        compute_stage(c);
    }

    // epilogue: y = acc + conv_b + residual; relu; dot out_w; reduce over o-tile
    const int quad = lane >> 2;   // 0..7
    const int pr   = lane & 3;    // 0..3
    const float* hb = hidden + (size_t)b * TLEN * HH;
    float* sred = (float*)sbuf;   // 128*4 floats
    __syncthreads();

    #pragma unroll
    for (int mf = 0; mf < 4; mf++) {
        int rloc = warp_m * 64 + mf * 16 + quad;
        float sA = 0.f, sB = 0.f;
        #pragma unroll
        for (int nf = 0; nf < 4; nf++) {
            int col = o0 + warp_n * 32 + nf * 8 + pr * 2;
            float2 cb = *(const float2*)(convb + col);
            float2 w  = *(const float2*)(outw + col);
            float2 hA = *(const float2*)(hb + (size_t)(t0 + rloc) * HH + col);
            float2 hB = *(const float2*)(hb + (size_t)(t0 + rloc + 8) * HH + col);
            float y;
            y = fmaxf(acc[mf][nf][0] + cb.x + hA.x, 0.f); sA = fmaf(y, w.x, sA);
            y = fmaxf(acc[mf][nf][1] + cb.y + hA.y, 0.f); sA = fmaf(y, w.y, sA);
            y = fmaxf(acc[mf][nf][2] + cb.x + hB.x, 0.f); sB = fmaf(y, w.x, sB);
            y = fmaxf(acc[mf][nf][3] + cb.y + hB.y, 0.f); sB = fmaf(y, w.y, sB);
        }
        sA += __shfl_xor_sync(0xffffffffu, sA, 1);
        sA += __shfl_xor_sync(0xffffffffu, sA, 2);
        sB += __shfl_xor_sync(0xffffffffu, sB, 1);
        sB += __shfl_xor_sync(0xffffffffu, sB, 2);
        if (pr == 0) {
            sred[rloc * 4 + warp_n]       = sA;
            sred[(rloc + 8) * 4 + warp_n] = sB;
        }
    }
    __syncthreads();
    if (tid < 128) {
        float s = (sred[tid*4+0] + sred[tid*4+1]) + (sred[tid*4+2] + sred[tid*4+3]);
        g_partial[(size_t)(b * TLEN + t0 + tid) * 4 + blockIdx.y] = s;
    }
}

// ------- fused alpha + sequential CIF scan (one block per batch) ----------
// 256 threads compute sigmoid-alpha into smem; thread 0 runs the EXACT
// fp32 serial scan (same arithmetic as before) out of smem.
__global__ __launch_bounds__(256, 1)
void k_ascan(const float* __restrict__ mask, const float* __restrict__ outb) {
    __shared__ __align__(16) float s_alpha[TLEN];
    const int b   = blockIdx.x;
    const int tid = threadIdx.x;
    const float ob = outb[0];

    #pragma unroll
    for (int it = 0; it < TLEN / 256; ++it) {
        int t = tid + it * 256;
        float4 p = *(const float4*)(g_partial + (size_t)(b * TLEN + t) * 4);
        float l = ((p.x + p.y) + (p.z + p.w)) + ob;
        float a = 1.f / (1.f + expf(-l));
        a = fmaxf(a, 0.f);
        a *= mask[b * TLEN + t];
        s_alpha[t] = a;
    }
    __syncthreads();

    if (tid != 0) return;
    const float4* al4 = (const float4*)s_alpha;
    float4* cur4 = (float4*)(g_cur + b * TLEN);
    int base = b * TLEN;
    float integ = 0.f;
    int j = 0;
    float4 c0 = al4[0], c1 = al4[1];
    #pragma unroll 1
    for (int ch = 0; ch < TLEN / 8; ++ch) {
        float4 n0 = make_float4(0,0,0,0), n1 = make_float4(0,0,0,0);
        if (ch + 1 < TLEN / 8) { n0 = al4[(ch+1)*2]; n1 = al4[(ch+1)*2 + 1]; }
        float av[8] = {c0.x,c0.y,c0.z,c0.w,c1.x,c1.y,c1.z,c1.w};
        float cv[8];
        int tt = ch * 8;
        #pragma unroll
        for (int s = 0; s < 8; s++) {
            float alpha = av[s];
            float dist  = 1.0f - integ;
            integ = integ + alpha;
            bool fire = (integ >= 1.0f);
            float cur = fire ? dist : alpha;
            cv[s] = cur;
            g_fire[base + j] = tt + s;        // unconditional; overwritten if !fire
            g_remv[base + j] = alpha - cur;
            j += fire;
            integ = fire ? integ - 1.0f : integ;
        }
        cur4[ch*2]   = make_float4(cv[0], cv[1], cv[2], cv[3]);
        cur4[ch*2+1] = make_float4(cv[4], cv[5], cv[6], cv[7]);
        c0 = n0; c1 = n1;
    }
    g_nf[b] = j;
}

// ---------------- parallel output gather (2048 blocks, loop batches) -------
__global__ void k_out(const float* __restrict__ hidden, float* __restrict__ out) {
    int j = blockIdx.x;
    int c = threadIdx.x << 2;
    #pragma unroll 1
    for (int b = 0; b < BB; ++b) {
        const float* hb = hidden + (size_t)b * TLEN * HH;
        float4 acc = make_float4(0.f, 0.f, 0.f, 0.f);
        if (j < g_nf[b]) {
            int tend = g_fire[b * TLEN + j];
            int ts = 0;
            if (j > 0) {
                int tp = g_fire[b * TLEN + j - 1];
                float rv = g_remv[b * TLEN + j - 1];
                float4 h = *(const float4*)(hb + (size_t)tp * HH + c);
                acc.x = rv * h.x; acc.y = rv * h.y; acc.z = rv * h.z; acc.w = rv * h.w;
                ts = tp + 1;
            }
            for (int t = ts; t <= tend; ++t) {
                float w = g_cur[b * TLEN + t];
                float4 h = *(const float4*)(hb + (size_t)t * HH + c);
                acc.x = fmaf(w, h.x, acc.x);
                acc.y = fmaf(w, h.y, acc.y);
                acc.z = fmaf(w, h.z, acc.z);
                acc.w = fmaf(w, h.w, acc.w);
            }
        }
        *(float4*)(out + (size_t)(b * TLEN + j) * HH + c) = acc;
    }
}

extern "C" void kernel_launch(void* const* d_in, const int* in_sizes, int n_in,
                              void* d_out, int out_size) {
    const float* hidden = (const float*)d_in[0];
    const float* mask   = (const float*)d_in[1];
    const float* conv_w = (const float*)d_in[2];
    const float* conv_b = (const float*)d_in[3];
    const float* out_w  = (const float*)d_in[4];
    const float* out_b  = (const float*)d_in[5];
    float* out = (float*)d_out;

    cudaFuncSetAttribute(k_gemm, cudaFuncAttributeMaxDynamicSharedMemorySize, DSMEM);

    k_hprep<<<(BT*HH/4 + 255)/256, 256>>>(hidden);
    k_wprep<<<(HH*KTOT + 255)/256, 256>>>(conv_w);
    dim3 gg(256, 4);
    k_gemm<<<gg, 256, DSMEM>>>(hidden, conv_b, out_w);
    k_ascan<<<BB, 256>>>(mask, out_b);
    k_out<<<TLEN, 128>>>(hidden, out);
}

// round 13
// speedup vs baseline: 1.2658x; 1.0051x over previous
#include <cuda_runtime.h>
#include <cuda_bf16.h>
#include <math.h>
#include <stdint.h>

#define BB 16
#define TLEN 2048
#define HH 512
#define BT (BB*TLEN)
#define KTOT 1536
#define NCH 32                // 32 channel-chunks of 16
#define NS 3                  // ring depth
// per-stage smem layout (bytes from stage base):
//   Ahi: 130 rows x 48B          [0, 6240)
//   Alo:                          [6240, 12480)
//   B  : 6 tensors (s*2+h) x 128 rows x 32B (chunk-XOR swizzled)
#define ST_ALO  6240
#define ST_B    12480
#define B_T     4096
#define STAGE_B (ST_B + 6*B_T)   // 37056
#define DSMEM   (NS*STAGE_B)     // 111168

// static device scratch (no allocations)
__device__ __nv_bfloat16 g_Ahi[(size_t)BT*HH];
__device__ __nv_bfloat16 g_Alo[(size_t)BT*HH];
__device__ __nv_bfloat16 g_Whi[HH*KTOT];   // [o][klin], klin = s*512+i
__device__ __nv_bfloat16 g_Wlo[HH*KTOT];
__device__ float g_partial[BT*4];
__device__ float g_cur[BT];
__device__ float g_remv[BT];
__device__ int   g_fire[BT];
__device__ int   g_nf[BB];

__device__ __forceinline__ uint32_t smem_u32(const void* p) {
    uint32_t r;
    asm("{ .reg .u64 t; cvta.to.shared.u64 t, %1; cvt.u32.u64 %0, t; }"
        : "=r"(r) : "l"(p));
    return r;
}
__device__ __forceinline__ void cp16(uint32_t dst, const void* src, int pb) {
    asm volatile("cp.async.cg.shared.global [%0], [%1], 16, %2;"
                 :: "r"(dst), "l"(src), "r"(pb));
}
__device__ __forceinline__ void ldx4(uint32_t* d, uint32_t addr) {
    asm volatile("ldmatrix.sync.aligned.m8n8.x4.shared.b16 {%0,%1,%2,%3}, [%4];"
                 : "=r"(d[0]), "=r"(d[1]), "=r"(d[2]), "=r"(d[3]) : "r"(addr));
}
#define MMA_BF16(c, a, b0, b1)                                              \
    asm volatile("mma.sync.aligned.m16n8k16.row.col.f32.bf16.bf16.f32 "     \
                 "{%0,%1,%2,%3}, {%4,%5,%6,%7}, {%8,%9}, {%0,%1,%2,%3};"    \
                 : "+f"((c)[0]), "+f"((c)[1]), "+f"((c)[2]), "+f"((c)[3])   \
                 : "r"((a)[0]), "r"((a)[1]), "r"((a)[2]), "r"((a)[3]),      \
                   "r"(b0), "r"(b1))

// ------------- prep: split hidden into bf16 hi/lo -------------
__global__ void k_hprep(const float* __restrict__ h) {
    size_t i = ((size_t)blockIdx.x * blockDim.x + threadIdx.x) * 4;
    float4 v = *(const float4*)(h + i);
    float vv[4] = {v.x, v.y, v.z, v.w};
    unsigned short hi[4], lo[4];
    #pragma unroll
    for (int k = 0; k < 4; k++) {
        __nv_bfloat16 hb = __float2bfloat16_rn(vv[k]);
        hi[k] = __bfloat16_as_ushort(hb);
        lo[k] = __bfloat16_as_ushort(__float2bfloat16_rn(vv[k] - __bfloat162float(hb)));
    }
    uint2 ph, pl;
    ph.x = (uint32_t)hi[0] | ((uint32_t)hi[1] << 16);
    ph.y = (uint32_t)hi[2] | ((uint32_t)hi[3] << 16);
    pl.x = (uint32_t)lo[0] | ((uint32_t)lo[1] << 16);
    pl.y = (uint32_t)lo[2] | ((uint32_t)lo[3] << 16);
    *(uint2*)(&g_Ahi[i]) = ph;
    *(uint2*)(&g_Alo[i]) = pl;
}

// ------------- prep: conv_w[o][i][s] -> Wt[o][s*512+i], bf16 hi/lo ---------
__global__ void k_wprep(const float* __restrict__ cw) {
    int idx = blockIdx.x * 256 + threadIdx.x;
    if (idx >= HH * KTOT) return;
    int o = idx / KTOT;
    int klin = idx % KTOT;
    int s = klin >> 9, i = klin & 511;
    float v = cw[(o * HH + i) * 3 + s];
    __nv_bfloat16 h = __float2bfloat16_rn(v);
    g_Whi[idx] = h;
    g_Wlo[idx] = __float2bfloat16_rn(v - __bfloat162float(h));
}

// ------------- bf16-split tensor-core GEMM (champion config) ----------
// CTA: 128 t x 128 o. 32 chunk-iters; 3-stage ring, depth-2 lookahead,
// one barrier/chunk, occ 2. B rows chunk-XOR swizzled -> conflict-free LDSM.
__global__ __launch_bounds__(256, 2)
void k_gemm(const float* __restrict__ hidden,
            const float* __restrict__ convb,
            const float* __restrict__ outw) {
    extern __shared__ __align__(16) unsigned char sbuf[];

    const int tid    = threadIdx.x;
    const int lane   = tid & 31;
    const int wid    = tid >> 5;
    const int warp_m = wid >> 2;     // 0..1
    const int warp_n = wid & 3;      // 0..3
    const int b      = blockIdx.x >> 4;
    const int t0     = (blockIdx.x & 15) * 128;
    const int o0     = blockIdx.y * 128;

    const __nv_bfloat16* Ahi = g_Ahi + (size_t)b * TLEN * HH;
    const __nv_bfloat16* Alo = g_Alo + (size_t)b * TLEN * HH;
    const uint32_t sb = smem_u32(sbuf);

    float acc[4][4][4];
    #pragma unroll
    for (int m = 0; m < 4; m++)
        #pragma unroll
        for (int n = 0; n < 4; n++)
            #pragma unroll
            for (int e = 0; e < 4; e++) acc[m][n][e] = 0.f;

    // ldmatrix lane->address selectors
    const int rowA = lane & 15;
    const int colA = (lane >> 4) << 3;
    const int rowB = (lane & 7) + ((lane >> 4) << 3);   // 0..15
    const int chunkB = (lane >> 3) & 1;                  // 16B chunk select
    const uint32_t rdoff = (uint32_t)(rowB * 32 + ((chunkB ^ ((rowB >> 2) & 1)) << 4));

    // B thread mapping (fixed per thread)
    const int browp = tid >> 1;        // 0..127
    const int bchk  = tid & 1;         // 16B chunk
    const uint32_t bwr = (uint32_t)(browp * 32 + ((bchk ^ ((browp >> 2) & 1)) << 4));

    auto load_stage = [&](int c) {
        const uint32_t st = sb + (uint32_t)(c % NS) * STAGE_B;
        const int i0 = c * 16;
        // A: 130 rows x 2 tensors x 2 chunks = 520 ops
        #pragma unroll
        for (int j = 0; j < 3; j++) {
            int a = tid + j * 256;
            if (a < 520) {
                int chunk  = a & 1;
                int tensor = (a >> 1) & 1;
                int row    = a >> 2;            // 0..129
                int gt = t0 - 1 + row;
                bool v = (gt >= 0) && (gt < TLEN);
                int gtc = v ? gt : 0;
                int pb  = v ? 16 : 0;
                const __nv_bfloat16* src =
                    (tensor ? Alo : Ahi) + (size_t)gtc * HH + i0 + chunk * 8;
                cp16(st + tensor * ST_ALO + row * 48 + chunk * 16, src, pb);
            }
        }
        // B: 6 tensors (s,h) x 128 rows x 2 chunks = 1536 ops
        #pragma unroll
        for (int j = 0; j < 6; j++) {
            int s = j >> 1, h = j & 1;
            const __nv_bfloat16* src =
                (h ? g_Wlo : g_Whi) + (size_t)(o0 + browp) * KTOT + s * 512 + i0 + bchk * 8;
            cp16(st + ST_B + j * B_T + bwr, src, 16);
        }
        asm volatile("cp.async.commit_group;");
    };

    auto compute_stage = [&](int c) {
        const uint32_t st = sb + (uint32_t)(c % NS) * STAGE_B;
        #pragma unroll
        for (int s = 0; s < 3; s++) {
            uint32_t aH[4][4], aL[4][4], bH[4][2], bL[4][2];
            #pragma unroll
            for (int mf = 0; mf < 4; mf++) {
                uint32_t off = (uint32_t)((warp_m * 64 + mf * 16 + rowA + s) * 48 + colA * 2);
                ldx4(aH[mf], st + off);
                ldx4(aL[mf], st + ST_ALO + off);
            }
            #pragma unroll
            for (int nh = 0; nh < 2; nh++) {
                uint32_t offb = (uint32_t)((warp_n * 32 + nh * 16) * 32) + rdoff;
                uint32_t d[4];
                ldx4(d, st + ST_B + (s * 2 + 0) * B_T + offb);
                bH[nh*2][0] = d[0]; bH[nh*2][1] = d[1];
                bH[nh*2+1][0] = d[2]; bH[nh*2+1][1] = d[3];
                ldx4(d, st + ST_B + (s * 2 + 1) * B_T + offb);
                bL[nh*2][0] = d[0]; bL[nh*2][1] = d[1];
                bL[nh*2+1][0] = d[2]; bL[nh*2+1][1] = d[3];
            }
            // term-major: per-accumulator order stays H*H -> H*L -> L*H
            #pragma unroll
            for (int mf = 0; mf < 4; mf++)
                #pragma unroll
                for (int nf = 0; nf < 4; nf++)
                    MMA_BF16(acc[mf][nf], aH[mf], bH[nf][0], bH[nf][1]);
            #pragma unroll
            for (int mf = 0; mf < 4; mf++)
                #pragma unroll
                for (int nf = 0; nf < 4; nf++)
                    MMA_BF16(acc[mf][nf], aH[mf], bL[nf][0], bL[nf][1]);
            #pragma unroll
            for (int mf = 0; mf < 4; mf++)
                #pragma unroll
                for (int nf = 0; nf < 4; nf++)
                    MMA_BF16(acc[mf][nf], aL[mf], bH[nf][0], bH[nf][1]);
        }
    };

    // prologue: depth-2 lookahead
    load_stage(0);
    load_stage(1);

    for (int c = 0; c < NCH; ++c) {
        asm volatile("cp.async.wait_group 1;");
        __syncthreads();
        if (c + 2 < NCH) {
            load_stage(c + 2);
        } else {
            asm volatile("cp.async.commit_group;");
        }
        compute_stage(c);
    }

    // epilogue: y = acc + conv_b + residual; relu; dot out_w; reduce over o-tile
    const int quad = lane >> 2;   // 0..7
    const int pr   = lane & 3;    // 0..3
    const float* hb = hidden + (size_t)b * TLEN * HH;
    float* sred = (float*)sbuf;   // 128*4 floats
    __syncthreads();

    #pragma unroll
    for (int mf = 0; mf < 4; mf++) {
        int rloc = warp_m * 64 + mf * 16 + quad;
        float sA = 0.f, sB = 0.f;
        #pragma unroll
        for (int nf = 0; nf < 4; nf++) {
            int col = o0 + warp_n * 32 + nf * 8 + pr * 2;
            float2 cb = *(const float2*)(convb + col);
            float2 w  = *(const float2*)(outw + col);
            float2 hA = *(const float2*)(hb + (size_t)(t0 + rloc) * HH + col);
            float2 hB = *(const float2*)(hb + (size_t)(t0 + rloc + 8) * HH + col);
            float y;
            y = fmaxf(acc[mf][nf][0] + cb.x + hA.x, 0.f); sA = fmaf(y, w.x, sA);
            y = fmaxf(acc[mf][nf][1] + cb.y + hA.y, 0.f); sA = fmaf(y, w.y, sA);
            y = fmaxf(acc[mf][nf][2] + cb.x + hB.x, 0.f); sB = fmaf(y, w.x, sB);
            y = fmaxf(acc[mf][nf][3] + cb.y + hB.y, 0.f); sB = fmaf(y, w.y, sB);
        }
        sA += __shfl_xor_sync(0xffffffffu, sA, 1);
        sA += __shfl_xor_sync(0xffffffffu, sA, 2);
        sB += __shfl_xor_sync(0xffffffffu, sB, 1);
        sB += __shfl_xor_sync(0xffffffffu, sB, 2);
        if (pr == 0) {
            sred[rloc * 4 + warp_n]       = sA;
            sred[(rloc + 8) * 4 + warp_n] = sB;
        }
    }
    __syncthreads();
    if (tid < 128) {
        float s = (sred[tid*4+0] + sred[tid*4+1]) + (sred[tid*4+2] + sred[tid*4+3]);
        g_partial[(size_t)(b * TLEN + t0 + tid) * 4 + blockIdx.y] = s;
    }
}

// ------- fused alpha + sequential CIF scan (one block per batch) ----------
// 256 threads compute sigmoid-alpha into smem; thread 0 runs the EXACT
// fp32 serial scan with ALL in-loop stores going to smem (STS issue-only);
// results are flushed to global cooperatively afterwards.
__global__ __launch_bounds__(256, 1)
void k_ascan(const float* __restrict__ mask, const float* __restrict__ outb) {
    __shared__ __align__(16) float s_alpha[TLEN];
    __shared__ __align__(16) float s_cur[TLEN];
    __shared__ __align__(16) float s_remv[TLEN];
    __shared__ __align__(16) int   s_fire[TLEN];
    __shared__ int s_nf;
    const int b   = blockIdx.x;
    const int tid = threadIdx.x;
    const float ob = outb[0];

    #pragma unroll
    for (int it = 0; it < TLEN / 256; ++it) {
        int t = tid + it * 256;
        float4 p = *(const float4*)(g_partial + (size_t)(b * TLEN + t) * 4);
        float l = ((p.x + p.y) + (p.z + p.w)) + ob;
        float a = 1.f / (1.f + expf(-l));
        a = fmaxf(a, 0.f);
        a *= mask[b * TLEN + t];
        s_alpha[t] = a;
    }
    __syncthreads();

    if (tid == 0) {
        const float4* al4 = (const float4*)s_alpha;
        float4* cur4 = (float4*)s_cur;
        float integ = 0.f;
        int j = 0;
        float4 c0 = al4[0], c1 = al4[1];
        #pragma unroll 1
        for (int ch = 0; ch < TLEN / 8; ++ch) {
            float4 n0 = make_float4(0,0,0,0), n1 = make_float4(0,0,0,0);
            if (ch + 1 < TLEN / 8) { n0 = al4[(ch+1)*2]; n1 = al4[(ch+1)*2 + 1]; }
            float av[8] = {c0.x,c0.y,c0.z,c0.w,c1.x,c1.y,c1.z,c1.w};
            float cv[8];
            int tt = ch * 8;
            #pragma unroll
            for (int s = 0; s < 8; s++) {
                float alpha = av[s];
                float dist  = 1.0f - integ;
                integ = integ + alpha;
                bool fire = (integ >= 1.0f);
                float cur = fire ? dist : alpha;
                cv[s] = cur;
                s_fire[j] = tt + s;        // STS; overwritten if !fire
                s_remv[j] = alpha - cur;
                j += fire;
                integ = fire ? integ - 1.0f : integ;
            }
            cur4[ch*2]   = make_float4(cv[0], cv[1], cv[2], cv[3]);
            cur4[ch*2+1] = make_float4(cv[4], cv[5], cv[6], cv[7]);
            c0 = n0; c1 = n1;
        }
        s_nf = j;
        g_nf[b] = j;
    }
    __syncthreads();

    // cooperative coalesced flush
    const int base = b * TLEN;
    float4* gc4 = (float4*)(g_cur + base);
    const float4* sc4 = (const float4*)s_cur;
    #pragma unroll
    for (int it = 0; it < TLEN / 4 / 256; ++it)
        gc4[tid + it * 256] = sc4[tid + it * 256];
    int nf = s_nf;
    for (int t = tid; t < nf; t += 256) {
        g_fire[base + t] = s_fire[t];
        g_remv[base + t] = s_remv[t];
    }
}

// ---------------- parallel output gather (2048 blocks, loop batches) -------
__global__ void k_out(const float* __restrict__ hidden, float* __restrict__ out) {
    int j = blockIdx.x;
    int c = threadIdx.x << 2;
    #pragma unroll 1
    for (int b = 0; b < BB; ++b) {
        const float* hb = hidden + (size_t)b * TLEN * HH;
        float4 acc = make_float4(0.f, 0.f, 0.f, 0.f);
        if (j < g_nf[b]) {
            int tend = g_fire[b * TLEN + j];
            int ts = 0;
            if (j > 0) {
                int tp = g_fire[b * TLEN + j - 1];
                float rv = g_remv[b * TLEN + j - 1];
                float4 h = *(const float4*)(hb + (size_t)tp * HH + c);
                acc.x = rv * h.x; acc.y = rv * h.y; acc.z = rv * h.z; acc.w = rv * h.w;
                ts = tp + 1;
            }
            for (int t = ts; t <= tend; ++t) {
                float w = g_cur[b * TLEN + t];
                float4 h = *(const float4*)(hb + (size_t)t * HH + c);
                acc.x = fmaf(w, h.x, acc.x);
                acc.y = fmaf(w, h.y, acc.y);
                acc.z = fmaf(w, h.z, acc.z);
                acc.w = fmaf(w, h.w, acc.w);
            }
        }
        *(float4*)(out + (size_t)(b * TLEN + j) * HH + c) = acc;
    }
}

extern "C" void kernel_launch(void* const* d_in, const int* in_sizes, int n_in,
                              void* d_out, int out_size) {
    const float* hidden = (const float*)d_in[0];
    const float* mask   = (const float*)d_in[1];
    const float* conv_w = (const float*)d_in[2];
    const float* conv_b = (const float*)d_in[3];
    const float* out_w  = (const float*)d_in[4];
    const float* out_b  = (const float*)d_in[5];
    float* out = (float*)d_out;

    cudaFuncSetAttribute(k_gemm, cudaFuncAttributeMaxDynamicSharedMemorySize, DSMEM);

    k_hprep<<<(BT*HH/4 + 255)/256, 256>>>(hidden);
    k_wprep<<<(HH*KTOT + 255)/256, 256>>>(conv_w);
    dim3 gg(256, 4);
    k_gemm<<<gg, 256, DSMEM>>>(hidden, conv_b, out_w);
    k_ascan<<<BB, 256>>>(mask, out_b);
    k_out<<<TLEN, 128>>>(hidden, out);
}

// round 14
// speedup vs baseline: 1.2843x; 1.0146x over previous
#include <cuda_runtime.h>
#include <cuda_bf16.h>
#include <math.h>
#include <stdint.h>

#define BB 16
#define TLEN 2048
#define HH 512
#define BT (BB*TLEN)
#define KTOT 1536
#define NCH 32                // 32 channel-chunks of 16
#define NS 3                  // ring depth
// per-stage smem layout (bytes from stage base):
//   Ahi: 130 rows x 48B          [0, 6240)
//   Alo:                          [6240, 12480)
//   B  : 6 tensors (s*2+h) x 128 rows x 32B (chunk-XOR swizzled)
#define ST_ALO  6240
#define ST_B    12480
#define B_T     4096
#define STAGE_B (ST_B + 6*B_T)   // 37056
#define DSMEM   (NS*STAGE_B)     // 111168

// static device scratch (no allocations)
__device__ __nv_bfloat16 g_Ahi[(size_t)BT*HH];
__device__ __nv_bfloat16 g_Alo[(size_t)BT*HH];
__device__ __nv_bfloat16 g_Whi[HH*KTOT];   // [o][klin], klin = s*512+i
__device__ __nv_bfloat16 g_Wlo[HH*KTOT];
__device__ float g_partial[BT*4];
__device__ float g_cur[BT];
__device__ float g_remv[BT];
__device__ int   g_fire[BT];
__device__ int   g_nf[BB];

__device__ __forceinline__ uint32_t smem_u32(const void* p) {
    uint32_t r;
    asm("{ .reg .u64 t; cvta.to.shared.u64 t, %1; cvt.u32.u64 %0, t; }"
        : "=r"(r) : "l"(p));
    return r;
}
__device__ __forceinline__ void cp16(uint32_t dst, const void* src, int pb) {
    asm volatile("cp.async.cg.shared.global [%0], [%1], 16, %2;"
                 :: "r"(dst), "l"(src), "r"(pb));
}
__device__ __forceinline__ void ldx4(uint32_t* d, uint32_t addr) {
    asm volatile("ldmatrix.sync.aligned.m8n8.x4.shared.b16 {%0,%1,%2,%3}, [%4];"
                 : "=r"(d[0]), "=r"(d[1]), "=r"(d[2]), "=r"(d[3]) : "r"(addr));
}
#define MMA_BF16(c, a, b0, b1)                                              \
    asm volatile("mma.sync.aligned.m16n8k16.row.col.f32.bf16.bf16.f32 "     \
                 "{%0,%1,%2,%3}, {%4,%5,%6,%7}, {%8,%9}, {%0,%1,%2,%3};"    \
                 : "+f"((c)[0]), "+f"((c)[1]), "+f"((c)[2]), "+f"((c)[3])   \
                 : "r"((a)[0]), "r"((a)[1]), "r"((a)[2]), "r"((a)[3]),      \
                   "r"(b0), "r"(b1))

// ------------- prep: split hidden into bf16 hi/lo -------------
__global__ void k_hprep(const float* __restrict__ h) {
    size_t i = ((size_t)blockIdx.x * blockDim.x + threadIdx.x) * 4;
    float4 v = *(const float4*)(h + i);
    float vv[4] = {v.x, v.y, v.z, v.w};
    unsigned short hi[4], lo[4];
    #pragma unroll
    for (int k = 0; k < 4; k++) {
        __nv_bfloat16 hb = __float2bfloat16_rn(vv[k]);
        hi[k] = __bfloat16_as_ushort(hb);
        lo[k] = __bfloat16_as_ushort(__float2bfloat16_rn(vv[k] - __bfloat162float(hb)));
    }
    uint2 ph, pl;
    ph.x = (uint32_t)hi[0] | ((uint32_t)hi[1] << 16);
    ph.y = (uint32_t)hi[2] | ((uint32_t)hi[3] << 16);
    pl.x = (uint32_t)lo[0] | ((uint32_t)lo[1] << 16);
    pl.y = (uint32_t)lo[2] | ((uint32_t)lo[3] << 16);
    *(uint2*)(&g_Ahi[i]) = ph;
    *(uint2*)(&g_Alo[i]) = pl;
}

// ------------- prep: conv_w[o][i][s] -> Wt[o][s*512+i], bf16 hi/lo ---------
__global__ void k_wprep(const float* __restrict__ cw) {
    int idx = blockIdx.x * 256 + threadIdx.x;
    if (idx >= HH * KTOT) return;
    int o = idx / KTOT;
    int klin = idx % KTOT;
    int s = klin >> 9, i = klin & 511;
    float v = cw[(o * HH + i) * 3 + s];
    __nv_bfloat16 h = __float2bfloat16_rn(v);
    g_Whi[idx] = h;
    g_Wlo[idx] = __float2bfloat16_rn(v - __bfloat162float(h));
}

// ------------- bf16-split tensor-core GEMM (champion config) ----------
// CTA: 128 t x 128 o. 32 chunk-iters; 3-stage ring, depth-2 lookahead,
// one barrier/chunk, occ 2. B rows chunk-XOR swizzled -> conflict-free LDSM.
__global__ __launch_bounds__(256, 2)
void k_gemm(const float* __restrict__ hidden,
            const float* __restrict__ convb,
            const float* __restrict__ outw) {
    extern __shared__ __align__(16) unsigned char sbuf[];

    const int tid    = threadIdx.x;
    const int lane   = tid & 31;
    const int wid    = tid >> 5;
    const int warp_m = wid >> 2;     // 0..1
    const int warp_n = wid & 3;      // 0..3
    const int b      = blockIdx.x >> 4;
    const int t0     = (blockIdx.x & 15) * 128;
    const int o0     = blockIdx.y * 128;

    const __nv_bfloat16* Ahi = g_Ahi + (size_t)b * TLEN * HH;
    const __nv_bfloat16* Alo = g_Alo + (size_t)b * TLEN * HH;
    const uint32_t sb = smem_u32(sbuf);

    float acc[4][4][4];
    #pragma unroll
    for (int m = 0; m < 4; m++)
        #pragma unroll
        for (int n = 0; n < 4; n++)
            #pragma unroll
            for (int e = 0; e < 4; e++) acc[m][n][e] = 0.f;

    // ldmatrix lane->address selectors
    const int rowA = lane & 15;
    const int colA = (lane >> 4) << 3;
    const int rowB = (lane & 7) + ((lane >> 4) << 3);   // 0..15
    const int chunkB = (lane >> 3) & 1;                  // 16B chunk select
    const uint32_t rdoff = (uint32_t)(rowB * 32 + ((chunkB ^ ((rowB >> 2) & 1)) << 4));

    // B thread mapping (fixed per thread)
    const int browp = tid >> 1;        // 0..127
    const int bchk  = tid & 1;         // 16B chunk
    const uint32_t bwr = (uint32_t)(browp * 32 + ((bchk ^ ((browp >> 2) & 1)) << 4));

    auto load_stage = [&](int c) {
        const uint32_t st = sb + (uint32_t)(c % NS) * STAGE_B;
        const int i0 = c * 16;
        // A: 130 rows x 2 tensors x 2 chunks = 520 ops
        #pragma unroll
        for (int j = 0; j < 3; j++) {
            int a = tid + j * 256;
            if (a < 520) {
                int chunk  = a & 1;
                int tensor = (a >> 1) & 1;
                int row    = a >> 2;            // 0..129
                int gt = t0 - 1 + row;
                bool v = (gt >= 0) && (gt < TLEN);
                int gtc = v ? gt : 0;
                int pb  = v ? 16 : 0;
                const __nv_bfloat16* src =
                    (tensor ? Alo : Ahi) + (size_t)gtc * HH + i0 + chunk * 8;
                cp16(st + tensor * ST_ALO + row * 48 + chunk * 16, src, pb);
            }
        }
        // B: 6 tensors (s,h) x 128 rows x 2 chunks = 1536 ops
        #pragma unroll
        for (int j = 0; j < 6; j++) {
            int s = j >> 1, h = j & 1;
            const __nv_bfloat16* src =
                (h ? g_Wlo : g_Whi) + (size_t)(o0 + browp) * KTOT + s * 512 + i0 + bchk * 8;
            cp16(st + ST_B + j * B_T + bwr, src, 16);
        }
        asm volatile("cp.async.commit_group;");
    };

    auto compute_stage = [&](int c) {
        const uint32_t st = sb + (uint32_t)(c % NS) * STAGE_B;
        #pragma unroll
        for (int s = 0; s < 3; s++) {
            uint32_t aH[4][4], aL[4][4], bH[4][2], bL[4][2];
            #pragma unroll
            for (int mf = 0; mf < 4; mf++) {
                uint32_t off = (uint32_t)((warp_m * 64 + mf * 16 + rowA + s) * 48 + colA * 2);
                ldx4(aH[mf], st + off);
                ldx4(aL[mf], st + ST_ALO + off);
            }
            #pragma unroll
            for (int nh = 0; nh < 2; nh++) {
                uint32_t offb = (uint32_t)((warp_n * 32 + nh * 16) * 32) + rdoff;
                uint32_t d[4];
                ldx4(d, st + ST_B + (s * 2 + 0) * B_T + offb);
                bH[nh*2][0] = d[0]; bH[nh*2][1] = d[1];
                bH[nh*2+1][0] = d[2]; bH[nh*2+1][1] = d[3];
                ldx4(d, st + ST_B + (s * 2 + 1) * B_T + offb);
                bL[nh*2][0] = d[0]; bL[nh*2][1] = d[1];
                bL[nh*2+1][0] = d[2]; bL[nh*2+1][1] = d[3];
            }
            // term-major: per-accumulator order stays H*H -> H*L -> L*H
            #pragma unroll
            for (int mf = 0; mf < 4; mf++)
                #pragma unroll
                for (int nf = 0; nf < 4; nf++)
                    MMA_BF16(acc[mf][nf], aH[mf], bH[nf][0], bH[nf][1]);
            #pragma unroll
            for (int mf = 0; mf < 4; mf++)
                #pragma unroll
                for (int nf = 0; nf < 4; nf++)
                    MMA_BF16(acc[mf][nf], aH[mf], bL[nf][0], bL[nf][1]);
            #pragma unroll
            for (int mf = 0; mf < 4; mf++)
                #pragma unroll
                for (int nf = 0; nf < 4; nf++)
                    MMA_BF16(acc[mf][nf], aL[mf], bH[nf][0], bH[nf][1]);
        }
    };

    // prologue: depth-2 lookahead
    load_stage(0);
    load_stage(1);

    for (int c = 0; c < NCH; ++c) {
        asm volatile("cp.async.wait_group 1;");
        __syncthreads();
        if (c + 2 < NCH) {
            load_stage(c + 2);
        } else {
            asm volatile("cp.async.commit_group;");
        }
        compute_stage(c);
    }

    // epilogue: y = acc + conv_b + residual; relu; dot out_w; reduce over o-tile
    const int quad = lane >> 2;   // 0..7
    const int pr   = lane & 3;    // 0..3
    const float* hb = hidden + (size_t)b * TLEN * HH;
    float* sred = (float*)sbuf;   // 128*4 floats
    __syncthreads();

    #pragma unroll
    for (int mf = 0; mf < 4; mf++) {
        int rloc = warp_m * 64 + mf * 16 + quad;
        float sA = 0.f, sB = 0.f;
        #pragma unroll
        for (int nf = 0; nf < 4; nf++) {
            int col = o0 + warp_n * 32 + nf * 8 + pr * 2;
            float2 cb = *(const float2*)(convb + col);
            float2 w  = *(const float2*)(outw + col);
            float2 hA = *(const float2*)(hb + (size_t)(t0 + rloc) * HH + col);
            float2 hB = *(const float2*)(hb + (size_t)(t0 + rloc + 8) * HH + col);
            float y;
            y = fmaxf(acc[mf][nf][0] + cb.x + hA.x, 0.f); sA = fmaf(y, w.x, sA);
            y = fmaxf(acc[mf][nf][1] + cb.y + hA.y, 0.f); sA = fmaf(y, w.y, sA);
            y = fmaxf(acc[mf][nf][2] + cb.x + hB.x, 0.f); sB = fmaf(y, w.x, sB);
            y = fmaxf(acc[mf][nf][3] + cb.y + hB.y, 0.f); sB = fmaf(y, w.y, sB);
        }
        sA += __shfl_xor_sync(0xffffffffu, sA, 1);
        sA += __shfl_xor_sync(0xffffffffu, sA, 2);
        sB += __shfl_xor_sync(0xffffffffu, sB, 1);
        sB += __shfl_xor_sync(0xffffffffu, sB, 2);
        if (pr == 0) {
            sred[rloc * 4 + warp_n]       = sA;
            sred[(rloc + 8) * 4 + warp_n] = sB;
        }
    }
    __syncthreads();
    if (tid < 128) {
        float s = (sred[tid*4+0] + sred[tid*4+1]) + (sred[tid*4+2] + sred[tid*4+3]);
        g_partial[(size_t)(b * TLEN + t0 + tid) * 4 + blockIdx.y] = s;
    }
}

// ------- fused alpha + sequential CIF scan (one block per batch) ----------
// 256 threads compute sigmoid-alpha into smem; thread 0 runs the serial scan
// with the predicate taken OFF the loop-carried chain:
//   integ' = integ + alpha;  firef = (integ' >= 1) ? 1.0f : 0.0f  (FSET, data)
//   integ  = integ' - firef          <- bit-identical to the ?: version
__global__ __launch_bounds__(256, 1)
void k_ascan(const float* __restrict__ mask, const float* __restrict__ outb) {
    __shared__ __align__(16) float s_alpha[TLEN];
    __shared__ __align__(16) float s_cur[TLEN];
    __shared__ __align__(16) float s_remv[TLEN];
    __shared__ __align__(16) int   s_fire[TLEN];
    __shared__ int s_nf;
    const int b   = blockIdx.x;
    const int tid = threadIdx.x;
    const float ob = outb[0];

    #pragma unroll
    for (int it = 0; it < TLEN / 256; ++it) {
        int t = tid + it * 256;
        float4 p = *(const float4*)(g_partial + (size_t)(b * TLEN + t) * 4);
        float l = ((p.x + p.y) + (p.z + p.w)) + ob;
        float a = 1.f / (1.f + expf(-l));
        a = fmaxf(a, 0.f);
        a *= mask[b * TLEN + t];
        s_alpha[t] = a;
    }
    __syncthreads();

    if (tid == 0) {
        const float4* al4 = (const float4*)s_alpha;
        float4* cur4 = (float4*)s_cur;
        float integ = 0.f;
        int j = 0;
        float4 c0 = al4[0], c1 = al4[1];
        #pragma unroll 1
        for (int ch = 0; ch < TLEN / 8; ++ch) {
            float4 n0 = make_float4(0,0,0,0), n1 = make_float4(0,0,0,0);
            if (ch + 1 < TLEN / 8) { n0 = al4[(ch+1)*2]; n1 = al4[(ch+1)*2 + 1]; }
            float av[8] = {c0.x,c0.y,c0.z,c0.w,c1.x,c1.y,c1.z,c1.w};
            float cv[8];
            int tt = ch * 8;
            #pragma unroll
            for (int s = 0; s < 8; s++) {
                float alpha = av[s];
                float dist  = 1.0f - integ;
                float integn = integ + alpha;
                // FSET: predicate as DATA (1.0f / 0.0f), latency 4 — keeps the
                // carried chain FADD->FSET->FADD (~12 cyc/step)
                float firef;
                asm("set.ge.f32.f32 %0, %1, %2;" : "=f"(firef) : "f"(integn), "f"(1.0f));
                bool fire = (integn >= 1.0f);      // FSETP, off the carried chain
                float cur = fire ? dist : alpha;
                cv[s] = cur;
                s_fire[j] = tt + s;                // STS; overwritten if !fire
                s_remv[j] = alpha - cur;
                j += fire;
                integ = integn - firef;            // exact: -1.0f or -0.0f
            }
            cur4[ch*2]   = make_float4(cv[0], cv[1], cv[2], cv[3]);
            cur4[ch*2+1] = make_float4(cv[4], cv[5], cv[6], cv[7]);
            c0 = n0; c1 = n1;
        }
        s_nf = j;
        g_nf[b] = j;
    }
    __syncthreads();

    // cooperative coalesced flush
    const int base = b * TLEN;
    float4* gc4 = (float4*)(g_cur + base);
    const float4* sc4 = (const float4*)s_cur;
    #pragma unroll
    for (int it = 0; it < TLEN / 4 / 256; ++it)
        gc4[tid + it * 256] = sc4[tid + it * 256];
    int nf = s_nf;
    for (int t = tid; t < nf; t += 256) {
        g_fire[base + t] = s_fire[t];
        g_remv[base + t] = s_remv[t];
    }
}

// ---------------- parallel output gather (2048 blocks, loop batches) -------
__global__ void k_out(const float* __restrict__ hidden, float* __restrict__ out) {
    int j = blockIdx.x;
    int c = threadIdx.x << 2;
    #pragma unroll 1
    for (int b = 0; b < BB; ++b) {
        const float* hb = hidden + (size_t)b * TLEN * HH;
        float4 acc = make_float4(0.f, 0.f, 0.f, 0.f);
        if (j < g_nf[b]) {
            int tend = g_fire[b * TLEN + j];
            int ts = 0;
            if (j > 0) {
                int tp = g_fire[b * TLEN + j - 1];
                float rv = g_remv[b * TLEN + j - 1];
                float4 h = *(const float4*)(hb + (size_t)tp * HH + c);
                acc.x = rv * h.x; acc.y = rv * h.y; acc.z = rv * h.z; acc.w = rv * h.w;
                ts = tp + 1;
            }
            for (int t = ts; t <= tend; ++t) {
                float w = g_cur[b * TLEN + t];
                float4 h = *(const float4*)(hb + (size_t)t * HH + c);
                acc.x = fmaf(w, h.x, acc.x);
                acc.y = fmaf(w, h.y, acc.y);
                acc.z = fmaf(w, h.z, acc.z);
                acc.w = fmaf(w, h.w, acc.w);
            }
        }
        *(float4*)(out + (size_t)(b * TLEN + j) * HH + c) = acc;
    }
}

extern "C" void kernel_launch(void* const* d_in, const int* in_sizes, int n_in,
                              void* d_out, int out_size) {
    const float* hidden = (const float*)d_in[0];
    const float* mask   = (const float*)d_in[1];
    const float* conv_w = (const float*)d_in[2];
    const float* conv_b = (const float*)d_in[3];
    const float* out_w  = (const float*)d_in[4];
    const float* out_b  = (const float*)d_in[5];
    float* out = (float*)d_out;

    cudaFuncSetAttribute(k_gemm, cudaFuncAttributeMaxDynamicSharedMemorySize, DSMEM);

    k_hprep<<<(BT*HH/4 + 255)/256, 256>>>(hidden);
    k_wprep<<<(HH*KTOT + 255)/256, 256>>>(conv_w);
    dim3 gg(256, 4);
    k_gemm<<<gg, 256, DSMEM>>>(hidden, conv_b, out_w);
    k_ascan<<<BB, 256>>>(mask, out_b);
    k_out<<<TLEN, 128>>>(hidden, out);
}

// round 15
// speedup vs baseline: 1.3259x; 1.0324x over previous
#include <cuda_runtime.h>
#include <cuda_bf16.h>
#include <math.h>
#include <stdint.h>

#define BB 16
#define TLEN 2048
#define HH 512
#define BT (BB*TLEN)
#define KTOT 1536
#define NCH 32                // 32 channel-chunks of 16
#define NS 3                  // ring depth
#define ST_ALO  6240
#define ST_B    12480
#define B_T     4096
#define STAGE_B (ST_B + 6*B_T)   // 37056
#define DSMEM   (NS*STAGE_B)     // 111168

// static device scratch (no allocations)
__device__ __nv_bfloat16 g_Ahi[(size_t)BT*HH];
__device__ __nv_bfloat16 g_Alo[(size_t)BT*HH];
__device__ __nv_bfloat16 g_Whi[HH*KTOT];   // [o][klin], klin = s*512+i
__device__ __nv_bfloat16 g_Wlo[HH*KTOT];
__device__ float g_partial[BT*4];
__device__ float g_cur[BT];
__device__ float g_remv[BT];
__device__ int   g_fire[BT];
__device__ int   g_nf[BB];

__device__ __forceinline__ uint32_t smem_u32(const void* p) {
    uint32_t r;
    asm("{ .reg .u64 t; cvta.to.shared.u64 t, %1; cvt.u32.u64 %0, t; }"
        : "=r"(r) : "l"(p));
    return r;
}
__device__ __forceinline__ void cp16(uint32_t dst, const void* src, int pb) {
    asm volatile("cp.async.cg.shared.global [%0], [%1], 16, %2;"
                 :: "r"(dst), "l"(src), "r"(pb));
}
__device__ __forceinline__ void ldx4(uint32_t* d, uint32_t addr) {
    asm volatile("ldmatrix.sync.aligned.m8n8.x4.shared.b16 {%0,%1,%2,%3}, [%4];"
                 : "=r"(d[0]), "=r"(d[1]), "=r"(d[2]), "=r"(d[3]) : "r"(addr));
}
#define MMA_BF16(c, a, b0, b1)                                              \
    asm volatile("mma.sync.aligned.m16n8k16.row.col.f32.bf16.bf16.f32 "     \
                 "{%0,%1,%2,%3}, {%4,%5,%6,%7}, {%8,%9}, {%0,%1,%2,%3};"    \
                 : "+f"((c)[0]), "+f"((c)[1]), "+f"((c)[2]), "+f"((c)[3])   \
                 : "r"((a)[0]), "r"((a)[1]), "r"((a)[2]), "r"((a)[3]),      \
                   "r"(b0), "r"(b1))

// ------------- prep: split hidden into bf16 hi/lo -------------
__global__ void k_hprep(const float* __restrict__ h) {
    size_t i = ((size_t)blockIdx.x * blockDim.x + threadIdx.x) * 4;
    float4 v = *(const float4*)(h + i);
    float vv[4] = {v.x, v.y, v.z, v.w};
    unsigned short hi[4], lo[4];
    #pragma unroll
    for (int k = 0; k < 4; k++) {
        __nv_bfloat16 hb = __float2bfloat16_rn(vv[k]);
        hi[k] = __bfloat16_as_ushort(hb);
        lo[k] = __bfloat16_as_ushort(__float2bfloat16_rn(vv[k] - __bfloat162float(hb)));
    }
    uint2 ph, pl;
    ph.x = (uint32_t)hi[0] | ((uint32_t)hi[1] << 16);
    ph.y = (uint32_t)hi[2] | ((uint32_t)hi[3] << 16);
    pl.x = (uint32_t)lo[0] | ((uint32_t)lo[1] << 16);
    pl.y = (uint32_t)lo[2] | ((uint32_t)lo[3] << 16);
    *(uint2*)(&g_Ahi[i]) = ph;
    *(uint2*)(&g_Alo[i]) = pl;
}

// ------------- prep: conv_w[o][i][s] -> Wt[o][s*512+i], bf16 hi/lo ---------
__global__ void k_wprep(const float* __restrict__ cw) {
    int idx = blockIdx.x * 256 + threadIdx.x;
    if (idx >= HH * KTOT) return;
    int o = idx / KTOT;
    int klin = idx % KTOT;
    int s = klin >> 9, i = klin & 511;
    float v = cw[(o * HH + i) * 3 + s];
    __nv_bfloat16 h = __float2bfloat16_rn(v);
    g_Whi[idx] = h;
    g_Wlo[idx] = __float2bfloat16_rn(v - __bfloat162float(h));
}

// ------------- bf16-split tensor-core GEMM (champion config) ----------
__global__ __launch_bounds__(256, 2)
void k_gemm(const float* __restrict__ hidden,
            const float* __restrict__ convb,
            const float* __restrict__ outw) {
    extern __shared__ __align__(16) unsigned char sbuf[];

    const int tid    = threadIdx.x;
    const int lane   = tid & 31;
    const int wid    = tid >> 5;
    const int warp_m = wid >> 2;     // 0..1
    const int warp_n = wid & 3;      // 0..3
    const int b      = blockIdx.x >> 4;
    const int t0     = (blockIdx.x & 15) * 128;
    const int o0     = blockIdx.y * 128;

    const __nv_bfloat16* Ahi = g_Ahi + (size_t)b * TLEN * HH;
    const __nv_bfloat16* Alo = g_Alo + (size_t)b * TLEN * HH;
    const uint32_t sb = smem_u32(sbuf);

    float acc[4][4][4];
    #pragma unroll
    for (int m = 0; m < 4; m++)
        #pragma unroll
        for (int n = 0; n < 4; n++)
            #pragma unroll
            for (int e = 0; e < 4; e++) acc[m][n][e] = 0.f;

    const int rowA = lane & 15;
    const int colA = (lane >> 4) << 3;
    const int rowB = (lane & 7) + ((lane >> 4) << 3);   // 0..15
    const int chunkB = (lane >> 3) & 1;                  // 16B chunk select
    const uint32_t rdoff = (uint32_t)(rowB * 32 + ((chunkB ^ ((rowB >> 2) & 1)) << 4));

    const int browp = tid >> 1;        // 0..127
    const int bchk  = tid & 1;         // 16B chunk
    const uint32_t bwr = (uint32_t)(browp * 32 + ((bchk ^ ((browp >> 2) & 1)) << 4));

    auto load_stage = [&](int c) {
        const uint32_t st = sb + (uint32_t)(c % NS) * STAGE_B;
        const int i0 = c * 16;
        #pragma unroll
        for (int j = 0; j < 3; j++) {
            int a = tid + j * 256;
            if (a < 520) {
                int chunk  = a & 1;
                int tensor = (a >> 1) & 1;
                int row    = a >> 2;            // 0..129
                int gt = t0 - 1 + row;
                bool v = (gt >= 0) && (gt < TLEN);
                int gtc = v ? gt : 0;
                int pb  = v ? 16 : 0;
                const __nv_bfloat16* src =
                    (tensor ? Alo : Ahi) + (size_t)gtc * HH + i0 + chunk * 8;
                cp16(st + tensor * ST_ALO + row * 48 + chunk * 16, src, pb);
            }
        }
        #pragma unroll
        for (int j = 0; j < 6; j++) {
            int s = j >> 1, h = j & 1;
            const __nv_bfloat16* src =
                (h ? g_Wlo : g_Whi) + (size_t)(o0 + browp) * KTOT + s * 512 + i0 + bchk * 8;
            cp16(st + ST_B + j * B_T + bwr, src, 16);
        }
        asm volatile("cp.async.commit_group;");
    };

    auto compute_stage = [&](int c) {
        const uint32_t st = sb + (uint32_t)(c % NS) * STAGE_B;
        #pragma unroll
        for (int s = 0; s < 3; s++) {
            uint32_t aH[4][4], aL[4][4], bH[4][2], bL[4][2];
            #pragma unroll
            for (int mf = 0; mf < 4; mf++) {
                uint32_t off = (uint32_t)((warp_m * 64 + mf * 16 + rowA + s) * 48 + colA * 2);
                ldx4(aH[mf], st + off);
                ldx4(aL[mf], st + ST_ALO + off);
            }
            #pragma unroll
            for (int nh = 0; nh < 2; nh++) {
                uint32_t offb = (uint32_t)((warp_n * 32 + nh * 16) * 32) + rdoff;
                uint32_t d[4];
                ldx4(d, st + ST_B + (s * 2 + 0) * B_T + offb);
                bH[nh*2][0] = d[0]; bH[nh*2][1] = d[1];
                bH[nh*2+1][0] = d[2]; bH[nh*2+1][1] = d[3];
                ldx4(d, st + ST_B + (s * 2 + 1) * B_T + offb);
                bL[nh*2][0] = d[0]; bL[nh*2][1] = d[1];
                bL[nh*2+1][0] = d[2]; bL[nh*2+1][1] = d[3];
            }
            #pragma unroll
            for (int mf = 0; mf < 4; mf++)
                #pragma unroll
                for (int nf = 0; nf < 4; nf++)
                    MMA_BF16(acc[mf][nf], aH[mf], bH[nf][0], bH[nf][1]);
            #pragma unroll
            for (int mf = 0; mf < 4; mf++)
                #pragma unroll
                for (int nf = 0; nf < 4; nf++)
                    MMA_BF16(acc[mf][nf], aH[mf], bL[nf][0], bL[nf][1]);
            #pragma unroll
            for (int mf = 0; mf < 4; mf++)
                #pragma unroll
                for (int nf = 0; nf < 4; nf++)
                    MMA_BF16(acc[mf][nf], aL[mf], bH[nf][0], bH[nf][1]);
        }
    };

    load_stage(0);
    load_stage(1);

    for (int c = 0; c < NCH; ++c) {
        asm volatile("cp.async.wait_group 1;");
        __syncthreads();
        if (c + 2 < NCH) {
            load_stage(c + 2);
        } else {
            asm volatile("cp.async.commit_group;");
        }
        compute_stage(c);
    }

    // epilogue
    const int quad = lane >> 2;   // 0..7
    const int pr   = lane & 3;    // 0..3
    const float* hb = hidden + (size_t)b * TLEN * HH;
    float* sred = (float*)sbuf;   // 128*4 floats
    __syncthreads();

    #pragma unroll
    for (int mf = 0; mf < 4; mf++) {
        int rloc = warp_m * 64 + mf * 16 + quad;
        float sA = 0.f, sB = 0.f;
        #pragma unroll
        for (int nf = 0; nf < 4; nf++) {
            int col = o0 + warp_n * 32 + nf * 8 + pr * 2;
            float2 cb = *(const float2*)(convb + col);
            float2 w  = *(const float2*)(outw + col);
            float2 hA = *(const float2*)(hb + (size_t)(t0 + rloc) * HH + col);
            float2 hB = *(const float2*)(hb + (size_t)(t0 + rloc + 8) * HH + col);
            float y;
            y = fmaxf(acc[mf][nf][0] + cb.x + hA.x, 0.f); sA = fmaf(y, w.x, sA);
            y = fmaxf(acc[mf][nf][1] + cb.y + hA.y, 0.f); sA = fmaf(y, w.y, sA);
            y = fmaxf(acc[mf][nf][2] + cb.x + hB.x, 0.f); sB = fmaf(y, w.x, sB);
            y = fmaxf(acc[mf][nf][3] + cb.y + hB.y, 0.f); sB = fmaf(y, w.y, sB);
        }
        sA += __shfl_xor_sync(0xffffffffu, sA, 1);
        sA += __shfl_xor_sync(0xffffffffu, sA, 2);
        sB += __shfl_xor_sync(0xffffffffu, sB, 1);
        sB += __shfl_xor_sync(0xffffffffu, sB, 2);
        if (pr == 0) {
            sred[rloc * 4 + warp_n]       = sA;
            sred[(rloc + 8) * 4 + warp_n] = sB;
        }
    }
    __syncthreads();
    if (tid < 128) {
        float s = (sred[tid*4+0] + sred[tid*4+1]) + (sred[tid*4+2] + sred[tid*4+3]);
        g_partial[(size_t)(b * TLEN + t0 + tid) * 4 + blockIdx.y] = s;
    }
}

// ------- fused alpha + split serial/parallel CIF scan ----------
// Phase 0: 256 threads compute alpha into smem.
// Phase A: thread 0 runs ONLY the carried recurrence, storing iprev per elem.
// Phase B: 256 threads recompute fire/cur/remv bit-identically (same FADD on
// same bits), block-prefix-scan fire counts for the compaction index, and
// write g_cur (coalesced) + scattered g_fire/g_remv.
__global__ __launch_bounds__(256, 1)
void k_ascan(const float* __restrict__ mask, const float* __restrict__ outb) {
    __shared__ __align__(16) float s_alpha[TLEN];
    __shared__ __align__(16) float s_iprev[TLEN];
    __shared__ int s_wsum[8];      // per-warp fire totals
    const int b    = blockIdx.x;
    const int tid  = threadIdx.x;
    const int lane = tid & 31;
    const int wrp  = tid >> 5;
    const float ob = outb[0];

    #pragma unroll
    for (int it = 0; it < TLEN / 256; ++it) {
        int t = tid + it * 256;
        float4 p = *(const float4*)(g_partial + (size_t)(b * TLEN + t) * 4);
        float l = ((p.x + p.y) + (p.z + p.w)) + ob;
        float a = 1.f / (1.f + expf(-l));
        a = fmaxf(a, 0.f);
        a *= mask[b * TLEN + t];
        s_alpha[t] = a;
    }
    __syncthreads();

    // ---- Phase A: minimal serial recurrence (thread 0) ----
    if (tid == 0) {
        const float4* al4 = (const float4*)s_alpha;
        float4* ip4 = (float4*)s_iprev;
        float integ = 0.f;
        float4 c0 = al4[0], c1 = al4[1];
        #pragma unroll 1
        for (int ch = 0; ch < TLEN / 8; ++ch) {
            float4 n0 = make_float4(0,0,0,0), n1 = make_float4(0,0,0,0);
            if (ch + 1 < TLEN / 8) { n0 = al4[(ch+1)*2]; n1 = al4[(ch+1)*2 + 1]; }
            float av[8] = {c0.x,c0.y,c0.z,c0.w,c1.x,c1.y,c1.z,c1.w};
            float pv[8];
            #pragma unroll
            for (int s = 0; s < 8; s++) {
                pv[s] = integ;                       // iprev for element
                float integn = integ + av[s];
                float firef;
                asm("set.ge.f32.f32 %0, %1, %2;" : "=f"(firef) : "f"(integn), "f"(1.0f));
                integ = integn - firef;              // exact: -1.0f or -0.0f
            }
            ip4[ch*2]   = make_float4(pv[0], pv[1], pv[2], pv[3]);
            ip4[ch*2+1] = make_float4(pv[4], pv[5], pv[6], pv[7]);
            c0 = n0; c1 = n1;
        }
    }
    __syncthreads();

    // ---- Phase B: parallel recomputation + compaction ----
    const int base = b * TLEN;
    const int t0 = tid * 8;
    float av[8], pv[8];
    *(float4*)&av[0] = *(const float4*)&s_alpha[t0];
    *(float4*)&av[4] = *(const float4*)&s_alpha[t0 + 4];
    *(float4*)&pv[0] = *(const float4*)&s_iprev[t0];
    *(float4*)&pv[4] = *(const float4*)&s_iprev[t0 + 4];

    int fcnt = 0;
    bool fires[8];
    float curs[8];
    #pragma unroll
    for (int s = 0; s < 8; s++) {
        float integn = pv[s] + av[s];        // identical FADD -> identical bits
        bool fire = (integn >= 1.0f);
        float dist = 1.0f - pv[s];
        curs[s] = fire ? dist : av[s];
        fires[s] = fire;
        fcnt += fire;
    }
    // warp inclusive scan of fcnt
    int inc = fcnt;
    #pragma unroll
    for (int d = 1; d < 32; d <<= 1) {
        int v = __shfl_up_sync(0xffffffffu, inc, d);
        if (lane >= d) inc += v;
    }
    if (lane == 31) s_wsum[wrp] = inc;
    __syncthreads();
    int wbase = 0;
    #pragma unroll
    for (int w = 0; w < 8; w++) wbase += (w < wrp) ? s_wsum[w] : 0;
    int j = wbase + inc - fcnt;              // exclusive prefix for this thread

    // coalesced g_cur writes
    *(float4*)(g_cur + base + t0)     = *(const float4*)&curs[0];
    *(float4*)(g_cur + base + t0 + 4) = *(const float4*)&curs[4];
    // scattered fire/remv writes in serial order
    #pragma unroll
    for (int s = 0; s < 8; s++) {
        if (fires[s]) {
            g_fire[base + j] = t0 + s;
            g_remv[base + j] = av[s] - curs[s];
            j++;
        }
    }
    if (tid == 255) g_nf[b] = wbase + inc;   // total fires
}

// ---------------- parallel output gather (2048 blocks, loop batches) -------
__global__ void k_out(const float* __restrict__ hidden, float* __restrict__ out) {
    int j = blockIdx.x;
    int c = threadIdx.x << 2;
    #pragma unroll 1
    for (int b = 0; b < BB; ++b) {
        const float* hb = hidden + (size_t)b * TLEN * HH;
        float4 acc = make_float4(0.f, 0.f, 0.f, 0.f);
        if (j < g_nf[b]) {
            int tend = g_fire[b * TLEN + j];
            int ts = 0;
            if (j > 0) {
                int tp = g_fire[b * TLEN + j - 1];
                float rv = g_remv[b * TLEN + j - 1];
                float4 h = *(const float4*)(hb + (size_t)tp * HH + c);
                acc.x = rv * h.x; acc.y = rv * h.y; acc.z = rv * h.z; acc.w = rv * h.w;
                ts = tp + 1;
            }
            for (int t = ts; t <= tend; ++t) {
                float w = g_cur[b * TLEN + t];
                float4 h = *(const float4*)(hb + (size_t)t * HH + c);
                acc.x = fmaf(w, h.x, acc.x);
                acc.y = fmaf(w, h.y, acc.y);
                acc.z = fmaf(w, h.z, acc.z);
                acc.w = fmaf(w, h.w, acc.w);
            }
        }
        *(float4*)(out + (size_t)(b * TLEN + j) * HH + c) = acc;
    }
}

extern "C" void kernel_launch(void* const* d_in, const int* in_sizes, int n_in,
                              void* d_out, int out_size) {
    const float* hidden = (const float*)d_in[0];
    const float* mask   = (const float*)d_in[1];
    const float* conv_w = (const float*)d_in[2];
    const float* conv_b = (const float*)d_in[3];
    const float* out_w  = (const float*)d_in[4];
    const float* out_b  = (const float*)d_in[5];
    float* out = (float*)d_out;

    cudaFuncSetAttribute(k_gemm, cudaFuncAttributeMaxDynamicSharedMemorySize, DSMEM);

    k_hprep<<<(BT*HH/4 + 255)/256, 256>>>(hidden);
    k_wprep<<<(HH*KTOT + 255)/256, 256>>>(conv_w);
    dim3 gg(256, 4);
    k_gemm<<<gg, 256, DSMEM>>>(hidden, conv_b, out_w);
    k_ascan<<<BB, 256>>>(mask, out_b);
    k_out<<<TLEN, 128>>>(hidden, out);
}

// round 16
// speedup vs baseline: 1.3386x; 1.0095x over previous
#include <cuda_runtime.h>
#include <cuda_bf16.h>
#include <math.h>
#include <stdint.h>

#define BB 16
#define TLEN 2048
#define HH 512
#define BT (BB*TLEN)
#define KTOT 1536
#define NCH 32                // 32 channel-chunks of 16
#define NS 3                  // ring depth
#define ST_ALO  6240
#define ST_B    12480
#define B_T     4096
#define STAGE_B (ST_B + 6*B_T)   // 37056
#define DSMEM   (NS*STAGE_B)     // 111168
#define HPREP_BLOCKS (BT*HH/4/256)   // 16384
#define WPREP_BLOCKS (HH*KTOT/256)   // 3072

// static device scratch (no allocations)
__device__ __nv_bfloat16 g_Ahi[(size_t)BT*HH];
__device__ __nv_bfloat16 g_Alo[(size_t)BT*HH];
__device__ __nv_bfloat16 g_Whi[HH*KTOT];   // [o][klin], klin = s*512+i
__device__ __nv_bfloat16 g_Wlo[HH*KTOT];
__device__ float g_partial[BT*4];
__device__ float g_cur[BT];
__device__ float g_remv[BT];
__device__ int   g_fire[BT];
__device__ int   g_nf[BB];

__device__ __forceinline__ uint32_t smem_u32(const void* p) {
    uint32_t r;
    asm("{ .reg .u64 t; cvta.to.shared.u64 t, %1; cvt.u32.u64 %0, t; }"
        : "=r"(r) : "l"(p));
    return r;
}
__device__ __forceinline__ void cp16(uint32_t dst, const void* src, int pb) {
    asm volatile("cp.async.cg.shared.global [%0], [%1], 16, %2;"
                 :: "r"(dst), "l"(src), "r"(pb));
}
__device__ __forceinline__ void ldx4(uint32_t* d, uint32_t addr) {
    asm volatile("ldmatrix.sync.aligned.m8n8.x4.shared.b16 {%0,%1,%2,%3}, [%4];"
                 : "=r"(d[0]), "=r"(d[1]), "=r"(d[2]), "=r"(d[3]) : "r"(addr));
}
#define MMA_BF16(c, a, b0, b1)                                              \
    asm volatile("mma.sync.aligned.m16n8k16.row.col.f32.bf16.bf16.f32 "     \
                 "{%0,%1,%2,%3}, {%4,%5,%6,%7}, {%8,%9}, {%0,%1,%2,%3};"    \
                 : "+f"((c)[0]), "+f"((c)[1]), "+f"((c)[2]), "+f"((c)[3])   \
                 : "r"((a)[0]), "r"((a)[1]), "r"((a)[2]), "r"((a)[3]),      \
                   "r"(b0), "r"(b1))

// ------------- merged prep: hidden split + weight re-layout/split ---------
__global__ void k_prep(const float* __restrict__ h, const float* __restrict__ cw) {
    if (blockIdx.x < HPREP_BLOCKS) {
        size_t i = ((size_t)blockIdx.x * 256 + threadIdx.x) * 4;
        float4 v = *(const float4*)(h + i);
        float vv[4] = {v.x, v.y, v.z, v.w};
        unsigned short hi[4], lo[4];
        #pragma unroll
        for (int k = 0; k < 4; k++) {
            __nv_bfloat16 hb = __float2bfloat16_rn(vv[k]);
            hi[k] = __bfloat16_as_ushort(hb);
            lo[k] = __bfloat16_as_ushort(__float2bfloat16_rn(vv[k] - __bfloat162float(hb)));
        }
        uint2 ph, pl;
        ph.x = (uint32_t)hi[0] | ((uint32_t)hi[1] << 16);
        ph.y = (uint32_t)hi[2] | ((uint32_t)hi[3] << 16);
        pl.x = (uint32_t)lo[0] | ((uint32_t)lo[1] << 16);
        pl.y = (uint32_t)lo[2] | ((uint32_t)lo[3] << 16);
        *(uint2*)(&g_Ahi[i]) = ph;
        *(uint2*)(&g_Alo[i]) = pl;
    } else {
        int idx = (blockIdx.x - HPREP_BLOCKS) * 256 + threadIdx.x;
        if (idx >= HH * KTOT) return;
        int o = idx / KTOT;
        int klin = idx % KTOT;
        int s = klin >> 9, i = klin & 511;
        float v = cw[(o * HH + i) * 3 + s];
        __nv_bfloat16 hb = __float2bfloat16_rn(v);
        g_Whi[idx] = hb;
        g_Wlo[idx] = __float2bfloat16_rn(v - __bfloat162float(hb));
    }
}

// ------------- bf16-split tensor-core GEMM (champion config) ----------
// Grid (4, 256): o-tile fast dim -> same-A CTAs co-scheduled (A L2 reuse).
__global__ __launch_bounds__(256, 2)
void k_gemm(const float* __restrict__ hidden,
            const float* __restrict__ convb,
            const float* __restrict__ outw) {
    extern __shared__ __align__(16) unsigned char sbuf[];

    const int tid    = threadIdx.x;
    const int lane   = tid & 31;
    const int wid    = tid >> 5;
    const int warp_m = wid >> 2;     // 0..1
    const int warp_n = wid & 3;      // 0..3
    const int b      = blockIdx.y >> 4;
    const int t0     = (blockIdx.y & 15) * 128;
    const int o0     = blockIdx.x * 128;

    const __nv_bfloat16* Ahi = g_Ahi + (size_t)b * TLEN * HH;
    const __nv_bfloat16* Alo = g_Alo + (size_t)b * TLEN * HH;
    const uint32_t sb = smem_u32(sbuf);

    float acc[4][4][4];
    #pragma unroll
    for (int m = 0; m < 4; m++)
        #pragma unroll
        for (int n = 0; n < 4; n++)
            #pragma unroll
            for (int e = 0; e < 4; e++) acc[m][n][e] = 0.f;

    const int rowA = lane & 15;
    const int colA = (lane >> 4) << 3;
    const int rowB = (lane & 7) + ((lane >> 4) << 3);   // 0..15
    const int chunkB = (lane >> 3) & 1;                  // 16B chunk select
    const uint32_t rdoff = (uint32_t)(rowB * 32 + ((chunkB ^ ((rowB >> 2) & 1)) << 4));

    const int browp = tid >> 1;        // 0..127
    const int bchk  = tid & 1;         // 16B chunk
    const uint32_t bwr = (uint32_t)(browp * 32 + ((bchk ^ ((browp >> 2) & 1)) << 4));

    auto load_stage = [&](int c) {
        const uint32_t st = sb + (uint32_t)(c % NS) * STAGE_B;
        const int i0 = c * 16;
        #pragma unroll
        for (int j = 0; j < 3; j++) {
            int a = tid + j * 256;
            if (a < 520) {
                int chunk  = a & 1;
                int tensor = (a >> 1) & 1;
                int row    = a >> 2;            // 0..129
                int gt = t0 - 1 + row;
                bool v = (gt >= 0) && (gt < TLEN);
                int gtc = v ? gt : 0;
                int pb  = v ? 16 : 0;
                const __nv_bfloat16* src =
                    (tensor ? Alo : Ahi) + (size_t)gtc * HH + i0 + chunk * 8;
                cp16(st + tensor * ST_ALO + row * 48 + chunk * 16, src, pb);
            }
        }
        #pragma unroll
        for (int j = 0; j < 6; j++) {
            int s = j >> 1, h = j & 1;
            const __nv_bfloat16* src =
                (h ? g_Wlo : g_Whi) + (size_t)(o0 + browp) * KTOT + s * 512 + i0 + bchk * 8;
            cp16(st + ST_B + j * B_T + bwr, src, 16);
        }
        asm volatile("cp.async.commit_group;");
    };

    auto compute_stage = [&](int c) {
        const uint32_t st = sb + (uint32_t)(c % NS) * STAGE_B;
        #pragma unroll
        for (int s = 0; s < 3; s++) {
            uint32_t aH[4][4], aL[4][4], bH[4][2], bL[4][2];
            #pragma unroll
            for (int mf = 0; mf < 4; mf++) {
                uint32_t off = (uint32_t)((warp_m * 64 + mf * 16 + rowA + s) * 48 + colA * 2);
                ldx4(aH[mf], st + off);
                ldx4(aL[mf], st + ST_ALO + off);
            }
            #pragma unroll
            for (int nh = 0; nh < 2; nh++) {
                uint32_t offb = (uint32_t)((warp_n * 32 + nh * 16) * 32) + rdoff;
                uint32_t d[4];
                ldx4(d, st + ST_B + (s * 2 + 0) * B_T + offb);
                bH[nh*2][0] = d[0]; bH[nh*2][1] = d[1];
                bH[nh*2+1][0] = d[2]; bH[nh*2+1][1] = d[3];
                ldx4(d, st + ST_B + (s * 2 + 1) * B_T + offb);
                bL[nh*2][0] = d[0]; bL[nh*2][1] = d[1];
                bL[nh*2+1][0] = d[2]; bL[nh*2+1][1] = d[3];
            }
            #pragma unroll
            for (int mf = 0; mf < 4; mf++)
                #pragma unroll
                for (int nf = 0; nf < 4; nf++)
                    MMA_BF16(acc[mf][nf], aH[mf], bH[nf][0], bH[nf][1]);
            #pragma unroll
            for (int mf = 0; mf < 4; mf++)
                #pragma unroll
                for (int nf = 0; nf < 4; nf++)
                    MMA_BF16(acc[mf][nf], aH[mf], bL[nf][0], bL[nf][1]);
            #pragma unroll
            for (int mf = 0; mf < 4; mf++)
                #pragma unroll
                for (int nf = 0; nf < 4; nf++)
                    MMA_BF16(acc[mf][nf], aL[mf], bH[nf][0], bH[nf][1]);
        }
    };

    load_stage(0);
    load_stage(1);

    for (int c = 0; c < NCH; ++c) {
        asm volatile("cp.async.wait_group 1;");
        __syncthreads();
        if (c + 2 < NCH) {
            load_stage(c + 2);
        } else {
            asm volatile("cp.async.commit_group;");
        }
        compute_stage(c);
    }

    // epilogue
    const int quad = lane >> 2;   // 0..7
    const int pr   = lane & 3;    // 0..3
    const float* hb = hidden + (size_t)b * TLEN * HH;
    float* sred = (float*)sbuf;   // 128*4 floats
    __syncthreads();

    #pragma unroll
    for (int mf = 0; mf < 4; mf++) {
        int rloc = warp_m * 64 + mf * 16 + quad;
        float sA = 0.f, sB = 0.f;
        #pragma unroll
        for (int nf = 0; nf < 4; nf++) {
            int col = o0 + warp_n * 32 + nf * 8 + pr * 2;
            float2 cb = *(const float2*)(convb + col);
            float2 w  = *(const float2*)(outw + col);
            float2 hA = *(const float2*)(hb + (size_t)(t0 + rloc) * HH + col);
            float2 hB = *(const float2*)(hb + (size_t)(t0 + rloc + 8) * HH + col);
            float y;
            y = fmaxf(acc[mf][nf][0] + cb.x + hA.x, 0.f); sA = fmaf(y, w.x, sA);
            y = fmaxf(acc[mf][nf][1] + cb.y + hA.y, 0.f); sA = fmaf(y, w.y, sA);
            y = fmaxf(acc[mf][nf][2] + cb.x + hB.x, 0.f); sB = fmaf(y, w.x, sB);
            y = fmaxf(acc[mf][nf][3] + cb.y + hB.y, 0.f); sB = fmaf(y, w.y, sB);
        }
        sA += __shfl_xor_sync(0xffffffffu, sA, 1);
        sA += __shfl_xor_sync(0xffffffffu, sA, 2);
        sB += __shfl_xor_sync(0xffffffffu, sB, 1);
        sB += __shfl_xor_sync(0xffffffffu, sB, 2);
        if (pr == 0) {
            sred[rloc * 4 + warp_n]       = sA;
            sred[(rloc + 8) * 4 + warp_n] = sB;
        }
    }
    __syncthreads();
    if (tid < 128) {
        float s = (sred[tid*4+0] + sred[tid*4+1]) + (sred[tid*4+2] + sred[tid*4+3]);
        g_partial[(size_t)(b * TLEN + t0 + tid) * 4 + blockIdx.x] = s;
    }
}

// ------- fused alpha + split serial/parallel CIF scan ----------
__global__ __launch_bounds__(256, 1)
void k_ascan(const float* __restrict__ mask, const float* __restrict__ outb) {
    __shared__ __align__(16) float s_alpha[TLEN];
    __shared__ __align__(16) float s_iprev[TLEN];
    __shared__ int s_wsum[8];      // per-warp fire totals
    const int b    = blockIdx.x;
    const int tid  = threadIdx.x;
    const int lane = tid & 31;
    const int wrp  = tid >> 5;
    const float ob = outb[0];

    #pragma unroll
    for (int it = 0; it < TLEN / 256; ++it) {
        int t = tid + it * 256;
        float4 p = *(const float4*)(g_partial + (size_t)(b * TLEN + t) * 4);
        float l = ((p.x + p.y) + (p.z + p.w)) + ob;
        float a = 1.f / (1.f + expf(-l));
        a = fmaxf(a, 0.f);
        a *= mask[b * TLEN + t];
        s_alpha[t] = a;
    }
    __syncthreads();

    // ---- Phase A: minimal serial recurrence (thread 0) ----
    if (tid == 0) {
        const float4* al4 = (const float4*)s_alpha;
        float4* ip4 = (float4*)s_iprev;
        float integ = 0.f;
        float4 c0 = al4[0], c1 = al4[1];
        #pragma unroll 1
        for (int ch = 0; ch < TLEN / 8; ++ch) {
            float4 n0 = make_float4(0,0,0,0), n1 = make_float4(0,0,0,0);
            if (ch + 1 < TLEN / 8) { n0 = al4[(ch+1)*2]; n1 = al4[(ch+1)*2 + 1]; }
            float av[8] = {c0.x,c0.y,c0.z,c0.w,c1.x,c1.y,c1.z,c1.w};
            float pv[8];
            #pragma unroll
            for (int s = 0; s < 8; s++) {
                pv[s] = integ;                       // iprev for element
                float integn = integ + av[s];
                float firef;
                asm("set.ge.f32.f32 %0, %1, %2;" : "=f"(firef) : "f"(integn), "f"(1.0f));
                integ = integn - firef;              // exact: -1.0f or -0.0f
            }
            ip4[ch*2]   = make_float4(pv[0], pv[1], pv[2], pv[3]);
            ip4[ch*2+1] = make_float4(pv[4], pv[5], pv[6], pv[7]);
            c0 = n0; c1 = n1;
        }
    }
    __syncthreads();

    // ---- Phase B: parallel recomputation + compaction ----
    const int base = b * TLEN;
    const int t0 = tid * 8;
    float av[8], pv[8];
    *(float4*)&av[0] = *(const float4*)&s_alpha[t0];
    *(float4*)&av[4] = *(const float4*)&s_alpha[t0 + 4];
    *(float4*)&pv[0] = *(const float4*)&s_iprev[t0];
    *(float4*)&pv[4] = *(const float4*)&s_iprev[t0 + 4];

    int fcnt = 0;
    bool fires[8];
    float curs[8];
    #pragma unroll
    for (int s = 0; s < 8; s++) {
        float integn = pv[s] + av[s];        // identical FADD -> identical bits
        bool fire = (integn >= 1.0f);
        float dist = 1.0f - pv[s];
        curs[s] = fire ? dist : av[s];
        fires[s] = fire;
        fcnt += fire;
    }
    int inc = fcnt;
    #pragma unroll
    for (int d = 1; d < 32; d <<= 1) {
        int v = __shfl_up_sync(0xffffffffu, inc, d);
        if (lane >= d) inc += v;
    }
    if (lane == 31) s_wsum[wrp] = inc;
    __syncthreads();
    int wbase = 0;
    #pragma unroll
    for (int w = 0; w < 8; w++) wbase += (w < wrp) ? s_wsum[w] : 0;
    int j = wbase + inc - fcnt;              // exclusive prefix for this thread

    *(float4*)(g_cur + base + t0)     = *(const float4*)&curs[0];
    *(float4*)(g_cur + base + t0 + 4) = *(const float4*)&curs[4];
    #pragma unroll
    for (int s = 0; s < 8; s++) {
        if (fires[s]) {
            g_fire[base + j] = t0 + s;
            g_remv[base + j] = av[s] - curs[s];
            j++;
        }
    }
    if (tid == 255) g_nf[b] = wbase + inc;   // total fires
}

// ---------------- parallel output gather (grid TLEN x 4, 4 batches/block) --
__global__ void k_out(const float* __restrict__ hidden, float* __restrict__ out) {
    int j = blockIdx.x;
    int c = threadIdx.x << 2;
    int b0 = blockIdx.y * 4;
    #pragma unroll 1
    for (int bi = 0; bi < 4; ++bi) {
        int b = b0 + bi;
        const float* hb = hidden + (size_t)b * TLEN * HH;
        float4 acc = make_float4(0.f, 0.f, 0.f, 0.f);
        if (j < g_nf[b]) {
            int tend = g_fire[b * TLEN + j];
            int ts = 0;
            if (j > 0) {
                int tp = g_fire[b * TLEN + j - 1];
                float rv = g_remv[b * TLEN + j - 1];
                float4 h = *(const float4*)(hb + (size_t)tp * HH + c);
                acc.x = rv * h.x; acc.y = rv * h.y; acc.z = rv * h.z; acc.w = rv * h.w;
                ts = tp + 1;
            }
            for (int t = ts; t <= tend; ++t) {
                float w = g_cur[b * TLEN + t];
                float4 h = *(const float4*)(hb + (size_t)t * HH + c);
                acc.x = fmaf(w, h.x, acc.x);
                acc.y = fmaf(w, h.y, acc.y);
                acc.z = fmaf(w, h.z, acc.z);
                acc.w = fmaf(w, h.w, acc.w);
            }
        }
        *(float4*)(out + (size_t)(b * TLEN + j) * HH + c) = acc;
    }
}

extern "C" void kernel_launch(void* const* d_in, const int* in_sizes, int n_in,
                              void* d_out, int out_size) {
    const float* hidden = (const float*)d_in[0];
    const float* mask   = (const float*)d_in[1];
    const float* conv_w = (const float*)d_in[2];
    const float* conv_b = (const float*)d_in[3];
    const float* out_w  = (const float*)d_in[4];
    const float* out_b  = (const float*)d_in[5];
    float* out = (float*)d_out;

    cudaFuncSetAttribute(k_gemm, cudaFuncAttributeMaxDynamicSharedMemorySize, DSMEM);

    k_prep<<<HPREP_BLOCKS + WPREP_BLOCKS, 256>>>(hidden, conv_w);
    dim3 gg(4, 256);
    k_gemm<<<gg, 256, DSMEM>>>(hidden, conv_b, out_w);
    k_ascan<<<BB, 256>>>(mask, out_b);
    dim3 go(TLEN, 4);
    k_out<<<go, 128>>>(hidden, out);
}

// round 17
// speedup vs baseline: 1.3441x; 1.0041x over previous
#include <cuda_runtime.h>
#include <cuda_bf16.h>
#include <math.h>
#include <stdint.h>

#define BB 16
#define TLEN 2048
#define HH 512
#define BT (BB*TLEN)
#define KTOT 1536
#define NCH 32                // 32 channel-chunks of 16
#define NS 3                  // ring depth
#define ST_ALO  6240
#define ST_B    12480
#define B_T     4096
#define STAGE_B (ST_B + 6*B_T)   // 37056
#define DSMEM   (NS*STAGE_B)     // 111168
#define HPREP_BLOCKS (BT*HH/4/256)   // 16384
#define WPREP_BLOCKS (HH*KTOT/256)   // 3072

// static device scratch (no allocations)
__device__ __nv_bfloat16 g_Ahi[(size_t)BT*HH];
__device__ __nv_bfloat16 g_Alo[(size_t)BT*HH];
__device__ __nv_bfloat16 g_Whi[HH*KTOT];   // [o][klin], klin = s*512+i
__device__ __nv_bfloat16 g_Wlo[HH*KTOT];
__device__ float g_partial[BT*4];
__device__ float g_cur[BT];
__device__ float g_remv[BT];
__device__ int   g_fire[BT];
__device__ int   g_nf[BB];

__device__ __forceinline__ uint32_t smem_u32(const void* p) {
    uint32_t r;
    asm("{ .reg .u64 t; cvta.to.shared.u64 t, %1; cvt.u32.u64 %0, t; }"
        : "=r"(r) : "l"(p));
    return r;
}
__device__ __forceinline__ void cp16(uint32_t dst, const void* src, int pb) {
    asm volatile("cp.async.cg.shared.global [%0], [%1], 16, %2;"
                 :: "r"(dst), "l"(src), "r"(pb));
}
__device__ __forceinline__ void ldx4(uint32_t* d, uint32_t addr) {
    asm volatile("ldmatrix.sync.aligned.m8n8.x4.shared.b16 {%0,%1,%2,%3}, [%4];"
                 : "=r"(d[0]), "=r"(d[1]), "=r"(d[2]), "=r"(d[3]) : "r"(addr));
}
#define MMA_BF16(c, a, b0, b1)                                              \
    asm volatile("mma.sync.aligned.m16n8k16.row.col.f32.bf16.bf16.f32 "     \
                 "{%0,%1,%2,%3}, {%4,%5,%6,%7}, {%8,%9}, {%0,%1,%2,%3};"    \
                 : "+f"((c)[0]), "+f"((c)[1]), "+f"((c)[2]), "+f"((c)[3])   \
                 : "r"((a)[0]), "r"((a)[1]), "r"((a)[2]), "r"((a)[3]),      \
                   "r"(b0), "r"(b1))

// ------------- merged prep: hidden split + weight re-layout/split ---------
__global__ void k_prep(const float* __restrict__ h, const float* __restrict__ cw) {
    if (blockIdx.x < HPREP_BLOCKS) {
        size_t i = ((size_t)blockIdx.x * 256 + threadIdx.x) * 4;
        float4 v = *(const float4*)(h + i);
        float vv[4] = {v.x, v.y, v.z, v.w};
        unsigned short hi[4], lo[4];
        #pragma unroll
        for (int k = 0; k < 4; k++) {
            __nv_bfloat16 hb = __float2bfloat16_rn(vv[k]);
            hi[k] = __bfloat16_as_ushort(hb);
            lo[k] = __bfloat16_as_ushort(__float2bfloat16_rn(vv[k] - __bfloat162float(hb)));
        }
        uint2 ph, pl;
        ph.x = (uint32_t)hi[0] | ((uint32_t)hi[1] << 16);
        ph.y = (uint32_t)hi[2] | ((uint32_t)hi[3] << 16);
        pl.x = (uint32_t)lo[0] | ((uint32_t)lo[1] << 16);
        pl.y = (uint32_t)lo[2] | ((uint32_t)lo[3] << 16);
        *(uint2*)(&g_Ahi[i]) = ph;
        *(uint2*)(&g_Alo[i]) = pl;
    } else {
        int idx = (blockIdx.x - HPREP_BLOCKS) * 256 + threadIdx.x;
        if (idx >= HH * KTOT) return;
        int o = idx / KTOT;
        int klin = idx % KTOT;
        int s = klin >> 9, i = klin & 511;
        float v = cw[(o * HH + i) * 3 + s];
        __nv_bfloat16 hb = __float2bfloat16_rn(v);
        g_Whi[idx] = hb;
        g_Wlo[idx] = __float2bfloat16_rn(v - __bfloat162float(hb));
    }
}

// ------------- bf16-split tensor-core GEMM (champion config) ----------
// Grid (4, 256): o-tile fast dim -> same-A CTAs co-scheduled (A L2 reuse).
__global__ __launch_bounds__(256, 2)
void k_gemm(const float* __restrict__ hidden,
            const float* __restrict__ convb,
            const float* __restrict__ outw) {
    extern __shared__ __align__(16) unsigned char sbuf[];

    const int tid    = threadIdx.x;
    const int lane   = tid & 31;
    const int wid    = tid >> 5;
    const int warp_m = wid >> 2;     // 0..1
    const int warp_n = wid & 3;      // 0..3
    const int b      = blockIdx.y >> 4;
    const int t0     = (blockIdx.y & 15) * 128;
    const int o0     = blockIdx.x * 128;

    const __nv_bfloat16* Ahi = g_Ahi + (size_t)b * TLEN * HH;
    const __nv_bfloat16* Alo = g_Alo + (size_t)b * TLEN * HH;
    const uint32_t sb = smem_u32(sbuf);

    float acc[4][4][4];
    #pragma unroll
    for (int m = 0; m < 4; m++)
        #pragma unroll
        for (int n = 0; n < 4; n++)
            #pragma unroll
            for (int e = 0; e < 4; e++) acc[m][n][e] = 0.f;

    const int rowA = lane & 15;
    const int colA = (lane >> 4) << 3;
    const int rowB = (lane & 7) + ((lane >> 4) << 3);   // 0..15
    const int chunkB = (lane >> 3) & 1;                  // 16B chunk select
    const uint32_t rdoff = (uint32_t)(rowB * 32 + ((chunkB ^ ((rowB >> 2) & 1)) << 4));

    const int browp = tid >> 1;        // 0..127
    const int bchk  = tid & 1;         // 16B chunk
    const uint32_t bwr = (uint32_t)(browp * 32 + ((bchk ^ ((browp >> 2) & 1)) << 4));

    auto load_stage = [&](int c) {
        const uint32_t st = sb + (uint32_t)(c % NS) * STAGE_B;
        const int i0 = c * 16;
        #pragma unroll
        for (int j = 0; j < 3; j++) {
            int a = tid + j * 256;
            if (a < 520) {
                int chunk  = a & 1;
                int tensor = (a >> 1) & 1;
                int row    = a >> 2;            // 0..129
                int gt = t0 - 1 + row;
                bool v = (gt >= 0) && (gt < TLEN);
                int gtc = v ? gt : 0;
                int pb  = v ? 16 : 0;
                const __nv_bfloat16* src =
                    (tensor ? Alo : Ahi) + (size_t)gtc * HH + i0 + chunk * 8;
                cp16(st + tensor * ST_ALO + row * 48 + chunk * 16, src, pb);
            }
        }
        #pragma unroll
        for (int j = 0; j < 6; j++) {
            int s = j >> 1, h = j & 1;
            const __nv_bfloat16* src =
                (h ? g_Wlo : g_Whi) + (size_t)(o0 + browp) * KTOT + s * 512 + i0 + bchk * 8;
            cp16(st + ST_B + j * B_T + bwr, src, 16);
        }
        asm volatile("cp.async.commit_group;");
    };

    auto compute_stage = [&](int c) {
        const uint32_t st = sb + (uint32_t)(c % NS) * STAGE_B;
        #pragma unroll
        for (int s = 0; s < 3; s++) {
            uint32_t aH[4][4], aL[4][4], bH[4][2], bL[4][2];
            #pragma unroll
            for (int mf = 0; mf < 4; mf++) {
                uint32_t off = (uint32_t)((warp_m * 64 + mf * 16 + rowA + s) * 48 + colA * 2);
                ldx4(aH[mf], st + off);
                ldx4(aL[mf], st + ST_ALO + off);
            }
            #pragma unroll
            for (int nh = 0; nh < 2; nh++) {
                uint32_t offb = (uint32_t)((warp_n * 32 + nh * 16) * 32) + rdoff;
                uint32_t d[4];
                ldx4(d, st + ST_B + (s * 2 + 0) * B_T + offb);
                bH[nh*2][0] = d[0]; bH[nh*2][1] = d[1];
                bH[nh*2+1][0] = d[2]; bH[nh*2+1][1] = d[3];
                ldx4(d, st + ST_B + (s * 2 + 1) * B_T + offb);
                bL[nh*2][0] = d[0]; bL[nh*2][1] = d[1];
                bL[nh*2+1][0] = d[2]; bL[nh*2+1][1] = d[3];
            }
            #pragma unroll
            for (int mf = 0; mf < 4; mf++)
                #pragma unroll
                for (int nf = 0; nf < 4; nf++)
                    MMA_BF16(acc[mf][nf], aH[mf], bH[nf][0], bH[nf][1]);
            #pragma unroll
            for (int mf = 0; mf < 4; mf++)
                #pragma unroll
                for (int nf = 0; nf < 4; nf++)
                    MMA_BF16(acc[mf][nf], aH[mf], bL[nf][0], bL[nf][1]);
            #pragma unroll
            for (int mf = 0; mf < 4; mf++)
                #pragma unroll
                for (int nf = 0; nf < 4; nf++)
                    MMA_BF16(acc[mf][nf], aL[mf], bH[nf][0], bH[nf][1]);
        }
    };

    load_stage(0);
    load_stage(1);

    // unroll 3: stage offsets (c % NS) become compile-time; body stays ~3
    // chunks of code -> fits I$ (guards against a full 32x unroll blowing it).
    #pragma unroll 3
    for (int c = 0; c < NCH; ++c) {
        asm volatile("cp.async.wait_group 1;");
        __syncthreads();
        if (c + 2 < NCH) {
            load_stage(c + 2);
        } else {
            asm volatile("cp.async.commit_group;");
        }
        compute_stage(c);
    }

    // epilogue
    const int quad = lane >> 2;   // 0..7
    const int pr   = lane & 3;    // 0..3
    const float* hb = hidden + (size_t)b * TLEN * HH;
    float* sred = (float*)sbuf;   // 128*4 floats
    __syncthreads();

    #pragma unroll
    for (int mf = 0; mf < 4; mf++) {
        int rloc = warp_m * 64 + mf * 16 + quad;
        float sA = 0.f, sB = 0.f;
        #pragma unroll
        for (int nf = 0; nf < 4; nf++) {
            int col = o0 + warp_n * 32 + nf * 8 + pr * 2;
            float2 cb = *(const float2*)(convb + col);
            float2 w  = *(const float2*)(outw + col);
            float2 hA = *(const float2*)(hb + (size_t)(t0 + rloc) * HH + col);
            float2 hB = *(const float2*)(hb + (size_t)(t0 + rloc + 8) * HH + col);
            float y;
            y = fmaxf(acc[mf][nf][0] + cb.x + hA.x, 0.f); sA = fmaf(y, w.x, sA);
            y = fmaxf(acc[mf][nf][1] + cb.y + hA.y, 0.f); sA = fmaf(y, w.y, sA);
            y = fmaxf(acc[mf][nf][2] + cb.x + hB.x, 0.f); sB = fmaf(y, w.x, sB);
            y = fmaxf(acc[mf][nf][3] + cb.y + hB.y, 0.f); sB = fmaf(y, w.y, sB);
        }
        sA += __shfl_xor_sync(0xffffffffu, sA, 1);
        sA += __shfl_xor_sync(0xffffffffu, sA, 2);
        sB += __shfl_xor_sync(0xffffffffu, sB, 1);
        sB += __shfl_xor_sync(0xffffffffu, sB, 2);
        if (pr == 0) {
            sred[rloc * 4 + warp_n]       = sA;
            sred[(rloc + 8) * 4 + warp_n] = sB;
        }
    }
    __syncthreads();
    if (tid < 128) {
        float s = (sred[tid*4+0] + sred[tid*4+1]) + (sred[tid*4+2] + sred[tid*4+3]);
        g_partial[(size_t)(b * TLEN + t0 + tid) * 4 + blockIdx.x] = s;
    }
}

// ------- fused alpha + split serial/parallel CIF scan ----------
__global__ __launch_bounds__(256, 1)
void k_ascan(const float* __restrict__ mask, const float* __restrict__ outb) {
    __shared__ __align__(16) float s_alpha[TLEN];
    __shared__ __align__(16) float s_iprev[TLEN];
    __shared__ int s_wsum[8];      // per-warp fire totals
    const int b    = blockIdx.x;
    const int tid  = threadIdx.x;
    const int lane = tid & 31;
    const int wrp  = tid >> 5;
    const float ob = outb[0];

    #pragma unroll
    for (int it = 0; it < TLEN / 256; ++it) {
        int t = tid + it * 256;
        float4 p = *(const float4*)(g_partial + (size_t)(b * TLEN + t) * 4);
        float l = ((p.x + p.y) + (p.z + p.w)) + ob;
        float a = 1.f / (1.f + expf(-l));
        a = fmaxf(a, 0.f);
        a *= mask[b * TLEN + t];
        s_alpha[t] = a;
    }
    __syncthreads();

    // ---- Phase A: minimal serial recurrence (thread 0) ----
    if (tid == 0) {
        const float4* al4 = (const float4*)s_alpha;
        float4* ip4 = (float4*)s_iprev;
        float integ = 0.f;
        float4 c0 = al4[0], c1 = al4[1];
        #pragma unroll 1
        for (int ch = 0; ch < TLEN / 8; ++ch) {
            float4 n0 = make_float4(0,0,0,0), n1 = make_float4(0,0,0,0);
            if (ch + 1 < TLEN / 8) { n0 = al4[(ch+1)*2]; n1 = al4[(ch+1)*2 + 1]; }
            float av[8] = {c0.x,c0.y,c0.z,c0.w,c1.x,c1.y,c1.z,c1.w};
            float pv[8];
            #pragma unroll
            for (int s = 0; s < 8; s++) {
                pv[s] = integ;                       // iprev for element
                float integn = integ + av[s];
                float firef;
                asm("set.ge.f32.f32 %0, %1, %2;" : "=f"(firef) : "f"(integn), "f"(1.0f));
                integ = integn - firef;              // exact: -1.0f or -0.0f
            }
            ip4[ch*2]   = make_float4(pv[0], pv[1], pv[2], pv[3]);
            ip4[ch*2+1] = make_float4(pv[4], pv[5], pv[6], pv[7]);
            c0 = n0; c1 = n1;
        }
    }
    __syncthreads();

    // ---- Phase B: parallel recomputation + compaction ----
    const int base = b * TLEN;
    const int t0 = tid * 8;
    float av[8], pv[8];
    *(float4*)&av[0] = *(const float4*)&s_alpha[t0];
    *(float4*)&av[4] = *(const float4*)&s_alpha[t0 + 4];
    *(float4*)&pv[0] = *(const float4*)&s_iprev[t0];
    *(float4*)&pv[4] = *(const float4*)&s_iprev[t0 + 4];

    int fcnt = 0;
    bool fires[8];
    float curs[8];
    #pragma unroll
    for (int s = 0; s < 8; s++) {
        float integn = pv[s] + av[s];        // identical FADD -> identical bits
        bool fire = (integn >= 1.0f);
        float dist = 1.0f - pv[s];
        curs[s] = fire ? dist : av[s];
        fires[s] = fire;
        fcnt += fire;
    }
    int inc = fcnt;
    #pragma unroll
    for (int d = 1; d < 32; d <<= 1) {
        int v = __shfl_up_sync(0xffffffffu, inc, d);
        if (lane >= d) inc += v;
    }
    if (lane == 31) s_wsum[wrp] = inc;
    __syncthreads();
    int wbase = 0;
    #pragma unroll
    for (int w = 0; w < 8; w++) wbase += (w < wrp) ? s_wsum[w] : 0;
    int j = wbase + inc - fcnt;              // exclusive prefix for this thread

    *(float4*)(g_cur + base + t0)     = *(const float4*)&curs[0];
    *(float4*)(g_cur + base + t0 + 4) = *(const float4*)&curs[4];
    #pragma unroll
    for (int s = 0; s < 8; s++) {
        if (fires[s]) {
            g_fire[base + j] = t0 + s;
            g_remv[base + j] = av[s] - curs[s];
            j++;
        }
    }
    if (tid == 255) g_nf[b] = wbase + inc;   // total fires
}

// ---------------- parallel output gather (grid TLEN x 16, 1 batch/block) ---
__global__ void k_out(const float* __restrict__ hidden, float* __restrict__ out) {
    int j = blockIdx.x;
    int b = blockIdx.y;
    int c = threadIdx.x << 2;
    const float* hb = hidden + (size_t)b * TLEN * HH;
    float4 acc = make_float4(0.f, 0.f, 0.f, 0.f);
    if (j < g_nf[b]) {
        int tend = g_fire[b * TLEN + j];
        int ts = 0;
        if (j > 0) {
            int tp = g_fire[b * TLEN + j - 1];
            float rv = g_remv[b * TLEN + j - 1];
            float4 h = *(const float4*)(hb + (size_t)tp * HH + c);
            acc.x = rv * h.x; acc.y = rv * h.y; acc.z = rv * h.z; acc.w = rv * h.w;
            ts = tp + 1;
        }
        for (int t = ts; t <= tend; ++t) {
            float w = g_cur[b * TLEN + t];
            float4 h = *(const float4*)(hb + (size_t)t * HH + c);
            acc.x = fmaf(w, h.x, acc.x);
            acc.y = fmaf(w, h.y, acc.y);
            acc.z = fmaf(w, h.z, acc.z);
            acc.w = fmaf(w, h.w, acc.w);
        }
    }
    *(float4*)(out + (size_t)(b * TLEN + j) * HH + c) = acc;
}

extern "C" void kernel_launch(void* const* d_in, const int* in_sizes, int n_in,
                              void* d_out, int out_size) {
    const float* hidden = (const float*)d_in[0];
    const float* mask   = (const float*)d_in[1];
    const float* conv_w = (const float*)d_in[2];
    const float* conv_b = (const float*)d_in[3];
    const float* out_w  = (const float*)d_in[4];
    const float* out_b  = (const float*)d_in[5];
    float* out = (float*)d_out;

    cudaFuncSetAttribute(k_gemm, cudaFuncAttributeMaxDynamicSharedMemorySize, DSMEM);

    k_prep<<<HPREP_BLOCKS + WPREP_BLOCKS, 256>>>(hidden, conv_w);
    dim3 gg(4, 256);
    k_gemm<<<gg, 256, DSMEM>>>(hidden, conv_b, out_w);
    k_ascan<<<BB, 256>>>(mask, out_b);
    dim3 go(TLEN, BB);
    k_out<<<go, 128>>>(hidden, out);
}